// round 2
// baseline (speedup 1.0000x reference)
#include <cuda_runtime.h>
#include <cstdint>

// Problem constants
#define NW        8192      // words
#define CL        16        // chars per word
#define CHID      128       // per-direction hidden
#define GATES     512       // 4*CHID
#define CDIM      64        // char embedding dim
#define WDIM      300       // word embedding dim
#define ODIM      512       // output dim
#define KPAD      576       // 556 padded to 9*64
#define KREAL     556

// ---------- device scratch (no cudaMalloc allowed) ----------
__device__ __align__(16) float g_P[2][128 * GATES];      // per-char gate preprojection (+bias)
__device__ __align__(16) float g_WhhT[2][CHID * GATES];  // Whh transposed [k][gate]
__device__ __align__(16) float g_WoutT[KPAD * ODIM];     // W_out transposed [d][o], zero-padded
__device__ __align__(16) float g_cf[NW * 256];           // summed bidir char features

// ---------- f32x2 helpers (Blackwell FFMA2: 2 IEEE fp32 FMA per issue) ----------
__device__ __forceinline__ unsigned long long dup2(float x) {
    unsigned long long r;
    asm("mov.b64 %0, {%1, %1};" : "=l"(r) : "f"(x));
    return r;
}
__device__ __forceinline__ unsigned long long pk2(float a, float b) {
    unsigned long long r;
    asm("mov.b64 %0, {%1, %2};" : "=l"(r) : "f"(a), "f"(b));
    return r;
}
__device__ __forceinline__ void upk2(unsigned long long v, float &a, float &b) {
    asm("mov.b64 {%0, %1}, %2;" : "=f"(a), "=f"(b) : "l"(v));
}
__device__ __forceinline__ void ffma2(unsigned long long &d, unsigned long long a,
                                      unsigned long long b) {
    asm("fma.rn.f32x2 %0, %1, %2, %0;" : "+l"(d) : "l"(a), "l"(b));
}

__device__ __forceinline__ float sigf(float x) {
    return __fdividef(1.0f, 1.0f + __expf(-x));
}
__device__ __forceinline__ float tanhf_fast(float x) {
    // tanh(x) = 2*sigmoid(2x)-1 ; __expf err ~2ulp -> abs err ~1e-6, far under 1e-3
    return 2.0f * __fdividef(1.0f, 1.0f + __expf(-2.0f * x)) - 1.0f;
}

// ---------- prep 1: P[dir][c][g] = char_table[c] . Wih[g] + bih[g] + bhh[g] ----------
__global__ void prep_P_kernel(const float *__restrict__ char_table,
                              const float *__restrict__ Wih_f, const float *__restrict__ bih_f,
                              const float *__restrict__ bhh_f,
                              const float *__restrict__ Wih_b, const float *__restrict__ bih_b,
                              const float *__restrict__ bhh_b) {
    int c = blockIdx.x, dir = blockIdx.y, tid = threadIdx.x;
    const float *Wih = dir ? Wih_b : Wih_f;
    const float *bi  = dir ? bih_b : bih_f;
    const float *bh  = dir ? bhh_b : bhh_f;
    __shared__ float cs[CDIM];
    if (tid < CDIM) cs[tid] = char_table[c * CDIM + tid];
    __syncthreads();
    for (int g = tid; g < GATES; g += blockDim.x) {
        float s = bi[g] + bh[g];
        const float *wr = Wih + g * CDIM;
#pragma unroll
        for (int d = 0; d < CDIM; ++d) s += cs[d] * wr[d];
        g_P[dir][c * GATES + g] = s;
    }
}

// ---------- prep 2: transposes (WhhT, WoutT with zero pad) ----------
__global__ void prep_T_kernel(const float *__restrict__ Whh_f,
                              const float *__restrict__ Whh_b,
                              const float *__restrict__ W_out) {
    int idx = blockIdx.x * blockDim.x + threadIdx.x;
    const int n_whh = 2 * CHID * GATES;  // 131072
    if (idx < n_whh) {
        int dir = idx >> 16;
        int r = idx & 65535;
        int k = r >> 9;       // 0..127
        int g = r & 511;
        const float *W = dir ? Whh_b : Whh_f;
        g_WhhT[dir][k * GATES + g] = W[g * CHID + k];
    } else {
        int j = idx - n_whh;
        if (j < KPAD * ODIM) {
            int d = j >> 9;   // 0..575
            int o = j & 511;
            g_WoutT[d * ODIM + o] = (d < KREAL) ? W_out[o * KREAL + d] : 0.0f;
        }
    }
}

// ---------- fused bidirectional char-LSTM ----------
// grid (128, 2): blockIdx.x -> 64-word tile, blockIdx.y -> direction.
// 512 threads: tid&15 -> word group (4 words), tid>>4 -> gate group (4 hidden j x 4 types).
// h kept in smem (transposed [j][word]); c and sum(h) in registers; WhhT staged in 64-row chunks.
#define LSTM_SMEM ((CHID * 64 + 64 * GATES) * 4 + 64 * CL * 4)

__global__ __launch_bounds__(512, 1) void lstm_kernel(const int *__restrict__ char_ids) {
    extern __shared__ float smem[];
    float *h_s = smem;                         // [128][64]
    float *w_s = smem + CHID * 64;             // [64][512]
    int *ci_s = (int *)(smem + CHID * 64 + 64 * GATES);  // [64][16]

    const int tid = threadIdx.x;
    const int dir = blockIdx.y;
    const int w_base = blockIdx.x * 64;
    const int wl0 = (tid & 15) * 4;   // local word base (0..60)
    const int j0 = (tid >> 4) * 4;    // hidden-j base (0..124)

    const float *Pd = g_P[dir];
    const float *WT = g_WhhT[dir];

    // stage char ids (contiguous [64 words][16])
    {
        const int *src = char_ids + (size_t)w_base * CL;
        ci_s[tid] = src[tid];
        ci_s[tid + 512] = src[tid + 512];
    }
    // zero h state
    {
        float4 *hz = (float4 *)h_s;
#pragma unroll
        for (int i = 0; i < 4; ++i) hz[tid + i * 512] = make_float4(0.f, 0.f, 0.f, 0.f);
    }
    float cst[4][4], hsum[4][4];
#pragma unroll
    for (int w = 0; w < 4; ++w)
#pragma unroll
        for (int j = 0; j < 4; ++j) { cst[w][j] = 0.f; hsum[w][j] = 0.f; }
    __syncthreads();

    unsigned long long acc2[4][8];  // [word][type*2 + pair]  (pair of consecutive j)

    for (int ti = 0; ti < CL; ++ti) {
        const int t = dir ? (CL - 1 - ti) : ti;

        // init gates from per-char preprojection (bias folded in)
#pragma unroll
        for (int w = 0; w < 4; ++w) {
            const int ch = ci_s[(wl0 + w) * CL + t];
            const float *Pr = Pd + ch * GATES;
#pragma unroll
            for (int ty = 0; ty < 4; ++ty) {
                float4 p = *(const float4 *)&Pr[ty * CHID + j0];
                acc2[w][ty * 2 + 0] = pk2(p.x, p.y);
                acc2[w][ty * 2 + 1] = pk2(p.z, p.w);
            }
        }

        // gates += h @ Whh^T, K staged in two 64-row chunks
#pragma unroll 1
        for (int kc = 0; kc < 2; ++kc) {
            __syncthreads();
            {
                const float4 *src = (const float4 *)(WT + kc * 64 * GATES);
                float4 *dst = (float4 *)w_s;
#pragma unroll
                for (int i = 0; i < 16; ++i) dst[tid + i * 512] = src[tid + i * 512];
            }
            __syncthreads();
#pragma unroll 4
            for (int k = 0; k < 64; ++k) {
                float4 h4 = *(const float4 *)&h_s[(kc * 64 + k) * 64 + wl0];
                unsigned long long hd0 = dup2(h4.x), hd1 = dup2(h4.y),
                                   hd2 = dup2(h4.z), hd3 = dup2(h4.w);
#pragma unroll
                for (int ty = 0; ty < 4; ++ty) {
                    ulonglong2 wv = *(const ulonglong2 *)&w_s[k * GATES + ty * CHID + j0];
                    ffma2(acc2[0][ty * 2 + 0], hd0, wv.x);
                    ffma2(acc2[0][ty * 2 + 1], hd0, wv.y);
                    ffma2(acc2[1][ty * 2 + 0], hd1, wv.x);
                    ffma2(acc2[1][ty * 2 + 1], hd1, wv.y);
                    ffma2(acc2[2][ty * 2 + 0], hd2, wv.x);
                    ffma2(acc2[2][ty * 2 + 1], hd2, wv.y);
                    ffma2(acc2[3][ty * 2 + 0], hd3, wv.x);
                    ffma2(acc2[3][ty * 2 + 1], hd3, wv.y);
                }
            }
        }
        __syncthreads();  // all h_s reads done before rewrite

        // pointwise LSTM cell + h sum + write h back (transposed)
#pragma unroll
        for (int w = 0; w < 4; ++w) {
            float ga[4][4];
#pragma unroll
            for (int ty = 0; ty < 4; ++ty) {
                upk2(acc2[w][ty * 2 + 0], ga[ty][0], ga[ty][1]);
                upk2(acc2[w][ty * 2 + 1], ga[ty][2], ga[ty][3]);
            }
#pragma unroll
            for (int jj = 0; jj < 4; ++jj) {
                float gi = sigf(ga[0][jj]);
                float gf = sigf(ga[1][jj]);
                float gg = tanhf_fast(ga[2][jj]);
                float go = sigf(ga[3][jj]);
                float cc = gf * cst[w][jj] + gi * gg;
                float hh = go * tanhf_fast(cc);
                cst[w][jj] = cc;
                hsum[w][jj] += hh;
                h_s[(j0 + jj) * 64 + wl0 + w] = hh;
            }
        }
    }

    // write summed features: cf[word][dir*128 + j]
#pragma unroll
    for (int w = 0; w < 4; ++w)
#pragma unroll
        for (int jj = 0; jj < 4; ++jj)
            g_cf[(size_t)(w_base + wl0 + w) * 256 + dir * CHID + j0 + jj] = hsum[w][jj];
}

// ---------- output GEMM: out = tanh([wordemb | cf] @ W_out^T + b_out) ----------
#define OUT_SMEM ((64 * 64 + 64 * ODIM) * 4 + 64 * 4)

__global__ __launch_bounds__(512, 1) void outgemm_kernel(const int *__restrict__ word_ids,
                                                         const float *__restrict__ word_table,
                                                         const float *__restrict__ b_out,
                                                         float *__restrict__ out) {
    extern __shared__ float smem[];
    float *feat_s = smem;                    // [64 k][64 w]
    float *w_s = smem + 64 * 64;             // [64 k][512 o]
    int *wid_s = (int *)(smem + 64 * 64 + 64 * ODIM);

    const int tid = threadIdx.x;
    const int w_base = blockIdx.x * 64;
    const int wl0 = (tid & 15) * 4;
    const int o0 = (tid >> 4) * 16;

    if (tid < 64) wid_s[tid] = word_ids[w_base + tid];
    __syncthreads();

    unsigned long long acc2[4][8];
#pragma unroll
    for (int w = 0; w < 4; ++w)
#pragma unroll
        for (int p = 0; p < 8; ++p) acc2[w][p] = 0ULL;

    const int wst = tid & 63;   // staging word
    const int kg = tid >> 6;    // staging k-group (8 k each)

#pragma unroll 1
    for (int kc = 0; kc < 9; ++kc) {
        __syncthreads();
        // stage feature chunk [64 k][64 w]
        {
            const int gw = w_base + wst;
            const int wid = wid_s[wst];
#pragma unroll
            for (int i = 0; i < 8; ++i) {
                int k = kg * 8 + i;
                int kk = kc * 64 + k;
                float v;
                if (kk < WDIM) v = word_table[(size_t)wid * WDIM + kk];
                else if (kk < KREAL) v = g_cf[(size_t)gw * 256 + (kk - WDIM)];
                else v = 0.0f;
                feat_s[k * 64 + wst] = v;
            }
        }
        // stage W chunk
        {
            const float4 *src = (const float4 *)(g_WoutT + kc * 64 * ODIM);
            float4 *dst = (float4 *)w_s;
#pragma unroll
            for (int i = 0; i < 16; ++i) dst[tid + i * 512] = src[tid + i * 512];
        }
        __syncthreads();
#pragma unroll 4
        for (int k = 0; k < 64; ++k) {
            float4 h4 = *(const float4 *)&feat_s[k * 64 + wl0];
            unsigned long long hd0 = dup2(h4.x), hd1 = dup2(h4.y),
                               hd2 = dup2(h4.z), hd3 = dup2(h4.w);
#pragma unroll
            for (int q = 0; q < 4; ++q) {
                ulonglong2 wv = *(const ulonglong2 *)&w_s[k * ODIM + o0 + q * 4];
                ffma2(acc2[0][q * 2 + 0], hd0, wv.x);
                ffma2(acc2[0][q * 2 + 1], hd0, wv.y);
                ffma2(acc2[1][q * 2 + 0], hd1, wv.x);
                ffma2(acc2[1][q * 2 + 1], hd1, wv.y);
                ffma2(acc2[2][q * 2 + 0], hd2, wv.x);
                ffma2(acc2[2][q * 2 + 1], hd2, wv.y);
                ffma2(acc2[3][q * 2 + 0], hd3, wv.x);
                ffma2(acc2[3][q * 2 + 1], hd3, wv.y);
            }
        }
    }

    // epilogue: bias + tanh + store
#pragma unroll
    for (int w = 0; w < 4; ++w) {
        const size_t row = (size_t)(w_base + wl0 + w) * ODIM;
#pragma unroll
        for (int q = 0; q < 4; ++q) {
            float v0, v1, v2, v3;
            upk2(acc2[w][q * 2 + 0], v0, v1);
            upk2(acc2[w][q * 2 + 1], v2, v3);
            float4 bo = *(const float4 *)&b_out[o0 + q * 4];
            float4 r;
            r.x = tanhf_fast(v0 + bo.x);
            r.y = tanhf_fast(v1 + bo.y);
            r.z = tanhf_fast(v2 + bo.z);
            r.w = tanhf_fast(v3 + bo.w);
            *(float4 *)&out[row + o0 + q * 4] = r;
        }
    }
}

// ---------- launch ----------
extern "C" void kernel_launch(void *const *d_in, const int *in_sizes, int n_in,
                              void *d_out, int out_size) {
    const int *word_ids     = (const int *)d_in[0];
    const int *char_ids     = (const int *)d_in[1];
    const float *word_table = (const float *)d_in[2];
    const float *char_table = (const float *)d_in[3];
    const float *Wih_f = (const float *)d_in[4];
    const float *Whh_f = (const float *)d_in[5];
    const float *bih_f = (const float *)d_in[6];
    const float *bhh_f = (const float *)d_in[7];
    const float *Wih_b = (const float *)d_in[8];
    const float *Whh_b = (const float *)d_in[9];
    const float *bih_b = (const float *)d_in[10];
    const float *bhh_b = (const float *)d_in[11];
    const float *W_out = (const float *)d_in[12];
    const float *b_out = (const float *)d_in[13];
    float *out = (float *)d_out;

    cudaFuncSetAttribute(lstm_kernel, cudaFuncAttributeMaxDynamicSharedMemorySize, LSTM_SMEM);
    cudaFuncSetAttribute(outgemm_kernel, cudaFuncAttributeMaxDynamicSharedMemorySize, OUT_SMEM);

    prep_P_kernel<<<dim3(128, 2), 128>>>(char_table, Wih_f, bih_f, bhh_f,
                                         Wih_b, bih_b, bhh_b);
    {
        const int total = 2 * CHID * GATES + KPAD * ODIM;  // 131072 + 294912
        prep_T_kernel<<<(total + 255) / 256, 256>>>(Whh_f, Whh_b, W_out);
    }
    lstm_kernel<<<dim3(128, 2), 512, LSTM_SMEM>>>(char_ids);
    outgemm_kernel<<<128, 512, OUT_SMEM>>>(word_ids, word_table, b_out, out);
}

// round 5
// speedup vs baseline: 5.3673x; 5.3673x over previous
#include <cuda_runtime.h>
#include <cuda_fp16.h>
#include <cstdint>

#define NW    8192
#define CL    16
#define CHID  128
#define GATES 512
#define CDIM  64
#define WDIM  300
#define ODIM  512
#define KPAD  576
#define KREAL 556

// ---------------- device scratch ----------------
__device__ __align__(16) float  g_P[2 * 128 * GATES];   // preproj [dir][ch][j*4+ty], bias folded
__device__ __align__(16) __half g_B[2][GATES * CHID];   // Whh fp16, row-permuted + XOR8 swizzle
__device__ __align__(16) float  g_WoutT[KPAD * ODIM];
__device__ __align__(16) float  g_cf[NW * 256];

// ---------------- helpers ----------------
__device__ __forceinline__ uint32_t smem_u32(const void* p) {
    uint32_t a;
    asm("{ .reg .u64 t; cvta.to.shared.u64 t, %1; cvt.u32.u64 %0, t; }" : "=r"(a) : "l"(p));
    return a;
}
__device__ __forceinline__ float sigf(float x) {
    return __fdividef(1.0f, 1.0f + __expf(-x));
}
__device__ __forceinline__ float tanhf_fast(float x) {
    return 2.0f * __fdividef(1.0f, 1.0f + __expf(-2.0f * x)) - 1.0f;
}
__device__ __forceinline__ unsigned long long dup2(float x) {
    unsigned long long r;
    asm("mov.b64 %0, {%1, %1};" : "=l"(r) : "f"(x));
    return r;
}
__device__ __forceinline__ void upk2(unsigned long long v, float& a, float& b) {
    asm("mov.b64 {%0, %1}, %2;" : "=f"(a), "=f"(b) : "l"(v));
}
__device__ __forceinline__ void ffma2(unsigned long long& d, unsigned long long a,
                                      unsigned long long b) {
    asm("fma.rn.f32x2 %0, %1, %2, %0;" : "+l"(d) : "l"(a), "l"(b));
}
__device__ __forceinline__ void ldm4(uint32_t* r, uint32_t addr) {
    asm volatile("ldmatrix.sync.aligned.m8n8.x4.shared.b16 {%0,%1,%2,%3}, [%4];"
                 : "=r"(r[0]), "=r"(r[1]), "=r"(r[2]), "=r"(r[3]) : "r"(addr));
}
__device__ __forceinline__ void mma16816(float* d, const uint32_t* a, uint32_t b0, uint32_t b1) {
    asm volatile("mma.sync.aligned.m16n8k16.row.col.f32.f16.f16.f32 "
                 "{%0,%1,%2,%3}, {%4,%5,%6,%7}, {%8,%9}, {%0,%1,%2,%3};"
                 : "+f"(d[0]), "+f"(d[1]), "+f"(d[2]), "+f"(d[3])
                 : "r"(a[0]), "r"(a[1]), "r"(a[2]), "r"(a[3]), "r"(b0), "r"(b1));
}

// ---------------- prep kernels ----------------
// P[dir][ch][j*4+ty] = char_table[ch] . Wih[ty*128+j] + bih + bhh
__global__ void prep_P(const float* __restrict__ ct,
                       const float* __restrict__ Wf, const float* __restrict__ bif,
                       const float* __restrict__ bhf,
                       const float* __restrict__ Wb, const float* __restrict__ bib,
                       const float* __restrict__ bhb) {
    int ch = blockIdx.x, dir = blockIdx.y, n = threadIdx.x;
    const float* W  = dir ? Wb : Wf;
    const float* bi = dir ? bib : bif;
    const float* bh = dir ? bhb : bhf;
    __shared__ float cs[CDIM];
    if (n < CDIM) cs[n] = ct[ch * CDIM + n];
    __syncthreads();
    int j = n >> 2, ty = n & 3, r = ty * CHID + j;
    float s = bi[r] + bh[r];
    const float* wr = W + r * CDIM;
#pragma unroll
    for (int d0 = 0; d0 < CDIM; ++d0) s += cs[d0] * wr[d0];
    g_P[(((dir << 7) + ch) << 9) + n] = s;
}

// Whh -> fp16, row rr = (j>>4)*64 + ty*16 + (j&15), XOR8 chunk swizzle within 256B rows
__global__ void prep_B(const float* __restrict__ Whh_f, const float* __restrict__ Whh_b) {
    int idx = blockIdx.x * blockDim.x + threadIdx.x;  // 131072
    int dir = idx >> 16;
    int rem = idx & 65535;
    int r0 = rem >> 7, k = rem & 127;     // original row ty*128+j
    int ty = r0 >> 7, j = r0 & 127;
    const float* W = dir ? Whh_b : Whh_f;
    float v = W[r0 * CHID + k];
    int rr = ((j >> 4) << 6) + (ty << 4) + (j & 15);
    int chunk = k >> 3;
    uint32_t off = (uint32_t)(rr * 256 + ((chunk ^ (rr & 7)) << 4) + (k & 7) * 2);
    *(__half*)((char*)g_B[dir] + off) = __float2half(v);
}

__global__ void prep_W(const float* __restrict__ W_out) {
    int idx = blockIdx.x * blockDim.x + threadIdx.x;
    if (idx < KPAD * ODIM) {
        int d = idx >> 9, o = idx & 511;
        g_WoutT[idx] = (d < KREAL) ? W_out[o * KREAL + d] : 0.0f;
    }
}

// ---------------- HMMA bidirectional char-LSTM ----------------
// grid (128, 2): 64 words/CTA, 1 dir. 512 threads = 16 warps: wm = wid>>3 (32-word half),
// wj = wid&7 (16-j block). Warp tile 32 words x 64 cols (16 j x 4 gate types).
#define CI_OFF 0
#define A_OFF  4096
#define B_OFF  20480
#define LSTM_SMEM (B_OFF + 131072)   // 151552

__global__ __launch_bounds__(512, 1) void lstm_kernel(const int* __restrict__ char_ids) {
    extern __shared__ char smem[];
    const uint32_t sb = smem_u32(smem);
    int* ci_s = (int*)(smem + CI_OFF);

    const int tid = threadIdx.x, wid = tid >> 5, lane = tid & 31;
    const int dir = blockIdx.y;
    const int w_base = blockIdx.x * 64;
    const int wm = wid >> 3, wj = wid & 7;

    // stage char ids, zero A(h0), stage B
    {
        const int* src = char_ids + (size_t)w_base * CL;
        ci_s[tid] = src[tid];
        ci_s[tid + 512] = src[tid + 512];
        float4* az = (float4*)(smem + A_OFF);
        az[tid] = make_float4(0.f, 0.f, 0.f, 0.f);
        az[tid + 512] = make_float4(0.f, 0.f, 0.f, 0.f);
        const float4* bsrc = (const float4*)g_B[dir];
        float4* bdst = (float4*)(smem + B_OFF);
#pragma unroll
        for (int i = 0; i < 16; ++i) bdst[tid + i * 512] = bsrc[tid + i * 512];
    }
    __syncthreads();

    // ldmatrix lane address bases
    const int asub = lane >> 3;
    const int arow0 = wm * 32 + ((asub & 1) << 3) + (lane & 7);   // + mt*16
    const int acp = asub >> 1;
    const int arm = arow0 & 7;
    const uint32_t a_base = sb + A_OFF + arow0 * 256;

    const int brow0 = wj * 64 + ((lane >> 4) << 3) + (lane & 7);  // + nb*16
    const int bcp = (lane >> 3) & 1;
    const int brm = brow0 & 7;
    const uint32_t b_base = sb + B_OFF + brow0 * 256;

    float d[2][8][4];
    float c_st[16], hs_st[16];
#pragma unroll
    for (int u = 0; u < 16; ++u) { c_st[u] = 0.f; hs_st[u] = 0.f; }

#pragma unroll 1
    for (int ti = 0; ti < CL; ++ti) {
        const int t = dir ? (CL - 1 - ti) : ti;

#pragma unroll
        for (int mt = 0; mt < 2; ++mt)
#pragma unroll
            for (int nt = 0; nt < 8; ++nt)
#pragma unroll
                for (int r = 0; r < 4; ++r) d[mt][nt][r] = 0.f;

        // gates = h(t-1) @ Whh^T  (K = 128, 8 k-steps)
#pragma unroll
        for (int ks = 0; ks < 8; ++ks) {
            uint32_t A0[4], A1[4];
            ldm4(A0, a_base + (((ks * 2 + acp) ^ arm) << 4));
            ldm4(A1, a_base + 16 * 256 + (((ks * 2 + acp) ^ arm) << 4));
#pragma unroll
            for (int nb = 0; nb < 4; ++nb) {
                uint32_t B[4];
                ldm4(B, b_base + nb * 16 * 256 + (((ks * 2 + bcp) ^ brm) << 4));
                mma16816(d[0][nb * 2 + 0], A0, B[0], B[1]);
                mma16816(d[0][nb * 2 + 1], A0, B[2], B[3]);
                mma16816(d[1][nb * 2 + 0], A1, B[0], B[1]);
                mma16816(d[1][nb * 2 + 1], A1, B[2], B[3]);
            }
        }
        __syncthreads();  // all A reads done before rewrite

        // epilogue: add P, activations, update c, sum h, write h(t) -> A
#pragma unroll
        for (int mt = 0; mt < 2; ++mt) {
#pragma unroll
            for (int rw = 0; rw < 2; ++rw) {
                const int wordl = wm * 32 + mt * 16 + (lane >> 2) + rw * 8;
                const int ch = ci_s[wordl * CL + t];
                const float4* Pf = (const float4*)(g_P + (((dir << 7) + ch) << 9));
#pragma unroll
                for (int jh = 0; jh < 2; ++jh) {
                    float hv[2];
#pragma unroll
                    for (int rj = 0; rj < 2; ++rj) {
                        const int jg = wj * 16 + jh * 8 + 2 * (lane & 3) + rj;
                        const float4 p = Pf[jg];
                        const int r = rw * 2 + rj;
                        const float gi = d[mt][0 + jh][r] + p.x;
                        const float gf = d[mt][2 + jh][r] + p.y;
                        const float gg = d[mt][4 + jh][r] + p.z;
                        const float go = d[mt][6 + jh][r] + p.w;
                        const int u = ((mt * 2 + rw) * 2 + jh) * 2 + rj;
                        const float cc = sigf(gf) * c_st[u] + sigf(gi) * tanhf_fast(gg);
                        c_st[u] = cc;
                        const float hh = sigf(go) * tanhf_fast(cc);
                        hs_st[u] += hh;
                        hv[rj] = hh;
                    }
                    const int k0 = wj * 16 + jh * 8 + 2 * (lane & 3);
                    const int chunk = k0 >> 3;
                    const uint32_t off =
                        (uint32_t)(wordl * 256 + ((chunk ^ (wordl & 7)) << 4) + (k0 & 7) * 2);
                    *(__half2*)(smem + A_OFF + off) = __floats2half2_rn(hv[0], hv[1]);
                }
            }
        }
        __syncthreads();  // h(t) visible for next step's ldmatrix
    }

    // write summed features
#pragma unroll
    for (int mt = 0; mt < 2; ++mt)
#pragma unroll
        for (int rw = 0; rw < 2; ++rw) {
            const int wordl = wm * 32 + mt * 16 + (lane >> 2) + rw * 8;
#pragma unroll
            for (int jh = 0; jh < 2; ++jh)
#pragma unroll
                for (int rj = 0; rj < 2; ++rj) {
                    const int jg = wj * 16 + jh * 8 + 2 * (lane & 3) + rj;
                    const int u = ((mt * 2 + rw) * 2 + jh) * 2 + rj;
                    g_cf[(size_t)(w_base + wordl) * 256 + dir * 128 + jg] = hs_st[u];
                }
        }
}

// ---------------- output GEMM (proven scalar FFMA2 path) ----------------
#define OUT_SMEM ((64 * 64 + 64 * ODIM) * 4 + 64 * 4)

__global__ __launch_bounds__(512, 1) void outgemm_kernel(const int* __restrict__ word_ids,
                                                         const float* __restrict__ word_table,
                                                         const float* __restrict__ b_out,
                                                         float* __restrict__ out) {
    extern __shared__ float smemf[];
    float* feat_s = smemf;
    float* w_s = smemf + 64 * 64;
    int* wid_s = (int*)(smemf + 64 * 64 + 64 * ODIM);

    const int tid = threadIdx.x;
    const int w_base = blockIdx.x * 64;
    const int wl0 = (tid & 15) * 4;
    const int o0 = (tid >> 4) * 16;

    if (tid < 64) wid_s[tid] = word_ids[w_base + tid];
    __syncthreads();

    unsigned long long acc2[4][8];
#pragma unroll
    for (int w = 0; w < 4; ++w)
#pragma unroll
        for (int p = 0; p < 8; ++p) acc2[w][p] = 0ULL;

    const int wst = tid & 63;
    const int kg = tid >> 6;

#pragma unroll 1
    for (int kc = 0; kc < 9; ++kc) {
        __syncthreads();
        {
            const int gw = w_base + wst;
            const int wid = wid_s[wst];
#pragma unroll
            for (int i = 0; i < 8; ++i) {
                int k = kg * 8 + i;
                int kk = kc * 64 + k;
                float v;
                if (kk < WDIM) v = word_table[(size_t)wid * WDIM + kk];
                else if (kk < KREAL) v = g_cf[(size_t)gw * 256 + (kk - WDIM)];
                else v = 0.0f;
                feat_s[k * 64 + wst] = v;
            }
        }
        {
            const float4* src = (const float4*)(g_WoutT + kc * 64 * ODIM);
            float4* dst = (float4*)w_s;
#pragma unroll
            for (int i = 0; i < 16; ++i) dst[tid + i * 512] = src[tid + i * 512];
        }
        __syncthreads();
#pragma unroll 4
        for (int k = 0; k < 64; ++k) {
            float4 h4 = *(const float4*)&feat_s[k * 64 + wl0];
            unsigned long long hd0 = dup2(h4.x), hd1 = dup2(h4.y),
                               hd2 = dup2(h4.z), hd3 = dup2(h4.w);
#pragma unroll
            for (int q = 0; q < 4; ++q) {
                ulonglong2 wv = *(const ulonglong2*)&w_s[k * ODIM + o0 + q * 4];
                ffma2(acc2[0][q * 2 + 0], hd0, wv.x);
                ffma2(acc2[0][q * 2 + 1], hd0, wv.y);
                ffma2(acc2[1][q * 2 + 0], hd1, wv.x);
                ffma2(acc2[1][q * 2 + 1], hd1, wv.y);
                ffma2(acc2[2][q * 2 + 0], hd2, wv.x);
                ffma2(acc2[2][q * 2 + 1], hd2, wv.y);
                ffma2(acc2[3][q * 2 + 0], hd3, wv.x);
                ffma2(acc2[3][q * 2 + 1], hd3, wv.y);
            }
        }
    }

#pragma unroll
    for (int w = 0; w < 4; ++w) {
        const size_t row = (size_t)(w_base + wl0 + w) * ODIM;
#pragma unroll
        for (int q = 0; q < 4; ++q) {
            float v0, v1, v2, v3;
            upk2(acc2[w][q * 2 + 0], v0, v1);
            upk2(acc2[w][q * 2 + 1], v2, v3);
            float4 bo = *(const float4*)&b_out[o0 + q * 4];
            float4 r;
            r.x = tanhf_fast(v0 + bo.x);
            r.y = tanhf_fast(v1 + bo.y);
            r.z = tanhf_fast(v2 + bo.z);
            r.w = tanhf_fast(v3 + bo.w);
            *(float4*)&out[row + o0 + q * 4] = r;
        }
    }
}

// ---------------- launch ----------------
extern "C" void kernel_launch(void* const* d_in, const int* in_sizes, int n_in,
                              void* d_out, int out_size) {
    const int* word_ids     = (const int*)d_in[0];
    const int* char_ids     = (const int*)d_in[1];
    const float* word_table = (const float*)d_in[2];
    const float* char_table = (const float*)d_in[3];
    const float* Wih_f = (const float*)d_in[4];
    const float* Whh_f = (const float*)d_in[5];
    const float* bih_f = (const float*)d_in[6];
    const float* bhh_f = (const float*)d_in[7];
    const float* Wih_b = (const float*)d_in[8];
    const float* Whh_b = (const float*)d_in[9];
    const float* bih_b = (const float*)d_in[10];
    const float* bhh_b = (const float*)d_in[11];
    const float* W_out = (const float*)d_in[12];
    const float* b_out = (const float*)d_in[13];
    float* out = (float*)d_out;

    cudaFuncSetAttribute(lstm_kernel, cudaFuncAttributeMaxDynamicSharedMemorySize, LSTM_SMEM);
    cudaFuncSetAttribute(outgemm_kernel, cudaFuncAttributeMaxDynamicSharedMemorySize, OUT_SMEM);

    prep_P<<<dim3(128, 2), 512>>>(char_table, Wih_f, bih_f, bhh_f, Wih_b, bih_b, bhh_b);
    prep_B<<<512, 256>>>(Whh_f, Whh_b);
    prep_W<<<(KPAD * ODIM + 255) / 256, 256>>>(W_out);
    lstm_kernel<<<dim3(128, 2), 512, LSTM_SMEM>>>(char_ids);
    outgemm_kernel<<<128, 512, OUT_SMEM>>>(word_ids, word_table, b_out, out);
}

// round 7
// speedup vs baseline: 7.2708x; 1.3547x over previous
#include <cuda_runtime.h>
#include <cuda_fp16.h>
#include <cstdint>

#define NW    8192
#define CL    16
#define CHID  128
#define GATES 512
#define CDIM  64
#define WDIM  300
#define ODIM  512
#define KREAL 556

// ---------------- device scratch ----------------
__device__ __align__(16) float  g_P[2 * 128 * GATES];   // preproj [dir][ch][j*4+ty], bias folded
__device__ __align__(16) __half g_B[2][GATES * CHID];   // Whh fp16, row-permuted + XOR8 swizzle
__device__ __align__(16) __half g_Wh[9 * 512 * 64];     // W_out hi fp16, 9 chunks, swizzled
__device__ __align__(16) __half g_Wl[9 * 512 * 64];     // W_out lo fp16
__device__ __align__(16) float  g_cf[NW * 256];

// ---------------- helpers ----------------
__device__ __forceinline__ uint32_t smem_u32(const void* p) {
    uint32_t a;
    asm("{ .reg .u64 t; cvta.to.shared.u64 t, %1; cvt.u32.u64 %0, t; }" : "=r"(a) : "l"(p));
    return a;
}
__device__ __forceinline__ float tanh_m(float x) {
    float y;
    asm("tanh.approx.f32 %0, %1;" : "=f"(y) : "f"(x));
    return y;
}
__device__ __forceinline__ float sig_m(float x) {
    return fmaf(0.5f, tanh_m(0.5f * x), 0.5f);
}
__device__ __forceinline__ float tanhf_fast(float x) {
    return 2.0f * __fdividef(1.0f, 1.0f + __expf(-2.0f * x)) - 1.0f;
}
__device__ __forceinline__ void ldm4(uint32_t* r, uint32_t addr) {
    asm volatile("ldmatrix.sync.aligned.m8n8.x4.shared.b16 {%0,%1,%2,%3}, [%4];"
                 : "=r"(r[0]), "=r"(r[1]), "=r"(r[2]), "=r"(r[3]) : "r"(addr));
}
__device__ __forceinline__ void mma16816(float* d, const uint32_t* a, uint32_t b0, uint32_t b1) {
    asm volatile("mma.sync.aligned.m16n8k16.row.col.f32.f16.f16.f32 "
                 "{%0,%1,%2,%3}, {%4,%5,%6,%7}, {%8,%9}, {%0,%1,%2,%3};"
                 : "+f"(d[0]), "+f"(d[1]), "+f"(d[2]), "+f"(d[3])
                 : "r"(a[0]), "r"(a[1]), "r"(a[2]), "r"(a[3]), "r"(b0), "r"(b1));
}

// ---------------- prep kernels ----------------
__global__ void prep_P(const float* __restrict__ ct,
                       const float* __restrict__ Wf, const float* __restrict__ bif,
                       const float* __restrict__ bhf,
                       const float* __restrict__ Wb, const float* __restrict__ bib,
                       const float* __restrict__ bhb) {
    int ch = blockIdx.x, dir = blockIdx.y, n = threadIdx.x;
    const float* W  = dir ? Wb : Wf;
    const float* bi = dir ? bib : bif;
    const float* bh = dir ? bhb : bhf;
    __shared__ float cs[CDIM];
    if (n < CDIM) cs[n] = ct[ch * CDIM + n];
    __syncthreads();
    int j = n >> 2, ty = n & 3, r = ty * CHID + j;
    float s = bi[r] + bh[r];
    const float* wr = W + r * CDIM;
#pragma unroll
    for (int d0 = 0; d0 < CDIM; ++d0) s += cs[d0] * wr[d0];
    g_P[(((dir << 7) + ch) << 9) + n] = s;
}

__global__ void prep_B(const float* __restrict__ Whh_f, const float* __restrict__ Whh_b) {
    int idx = blockIdx.x * blockDim.x + threadIdx.x;  // 131072
    int dir = idx >> 16;
    int rem = idx & 65535;
    int r0 = rem >> 7, k = rem & 127;
    int ty = r0 >> 7, j = r0 & 127;
    const float* W = dir ? Whh_b : Whh_f;
    float v = W[r0 * CHID + k];
    int rr = ((j >> 4) << 6) + (ty << 4) + (j & 15);
    int chunk = k >> 3;
    uint32_t off = (uint32_t)(rr * 256 + ((chunk ^ (rr & 7)) << 4) + (k & 7) * 2);
    *(__half*)((char*)g_B[dir] + off) = __float2half(v);
}

__global__ void prep_Wsplit(const float* __restrict__ W_out) {
    int idx = blockIdx.x * blockDim.x + threadIdx.x;  // 294912
    if (idx >= 9 * 512 * 64) return;
    int kc = idx >> 15;
    int n = (idx >> 6) & 511;
    int k = idx & 63;
    int kk = kc * 64 + k;
    float v = (kk < KREAL) ? W_out[n * KREAL + kk] : 0.0f;
    __half hi = __float2half(v);
    __half lo = __float2half(v - __half2float(hi));
    uint32_t off = (uint32_t)(kc * 65536 + n * 128 + (((k >> 3) ^ (n & 7)) << 4) + (k & 7) * 2);
    *(__half*)((char*)g_Wh + off) = hi;
    *(__half*)((char*)g_Wl + off) = lo;
}

// ---------------- HMMA bidirectional char-LSTM ----------------
#define CI_OFF 0
#define A_OFF  4096          // 2 buffers x 16384
#define B_OFF  36864
#define LSTM_SMEM (B_OFF + 131072)   // 167936

__global__ __launch_bounds__(512, 1) void lstm_kernel(const int* __restrict__ char_ids) {
    extern __shared__ char smem[];
    const uint32_t sb = smem_u32(smem);
    int* ci_s = (int*)(smem + CI_OFF);

    const int tid = threadIdx.x, wid = tid >> 5, lane = tid & 31;
    const int dir = blockIdx.y;
    const int w_base = blockIdx.x * 64;
    const int wm = wid >> 3, wj = wid & 7;

    {
        const int* src = char_ids + (size_t)w_base * CL;
        ci_s[tid] = src[tid];
        ci_s[tid + 512] = src[tid + 512];
        float4* az = (float4*)(smem + A_OFF);
        az[tid] = make_float4(0.f, 0.f, 0.f, 0.f);
        az[tid + 512] = make_float4(0.f, 0.f, 0.f, 0.f);
        const float4* bsrc = (const float4*)g_B[dir];
        float4* bdst = (float4*)(smem + B_OFF);
#pragma unroll
        for (int i = 0; i < 16; ++i) bdst[tid + i * 512] = bsrc[tid + i * 512];
    }
    __syncthreads();

    const int asub = lane >> 3;
    const int arow0 = wm * 32 + ((asub & 1) << 3) + (lane & 7);
    const int acp = asub >> 1;
    const int arm = arow0 & 7;

    const int brow0 = wj * 64 + ((lane >> 4) << 3) + (lane & 7);
    const int bcp = (lane >> 3) & 1;
    const int brm = brow0 & 7;
    const uint32_t b_base = sb + B_OFF + brow0 * 256;

    float d[2][8][4];
    float c_st[16], hs_st[16];
#pragma unroll
    for (int u = 0; u < 16; ++u) { c_st[u] = 0.f; hs_st[u] = 0.f; }

#pragma unroll 1
    for (int ti = 0; ti < CL; ++ti) {
        const int t = dir ? (CL - 1 - ti) : ti;
        const uint32_t rbuf = (uint32_t)(ti & 1) << 14;
        const uint32_t wbuf = rbuf ^ 16384u;
        const uint32_t a_base = sb + A_OFF + rbuf + arow0 * 256;

        // init accumulators from P (L2 loads overlap with tensor work)
#pragma unroll
        for (int mt = 0; mt < 2; ++mt)
#pragma unroll
            for (int rw = 0; rw < 2; ++rw) {
                const int wordl = wm * 32 + mt * 16 + (lane >> 2) + rw * 8;
                const int ch = ci_s[wordl * CL + t];
                const float4* Pf = (const float4*)(g_P + (((dir << 7) + ch) << 9));
#pragma unroll
                for (int jh = 0; jh < 2; ++jh)
#pragma unroll
                    for (int rj = 0; rj < 2; ++rj) {
                        const int jg = wj * 16 + jh * 8 + 2 * (lane & 3) + rj;
                        const float4 p = Pf[jg];
                        const int r = rw * 2 + rj;
                        d[mt][0 + jh][r] = p.x;
                        d[mt][2 + jh][r] = p.y;
                        d[mt][4 + jh][r] = p.z;
                        d[mt][6 + jh][r] = p.w;
                    }
            }

        // gates += h(t-1) @ Whh^T
#pragma unroll
        for (int ks = 0; ks < 8; ++ks) {
            uint32_t A0[4], A1[4];
            ldm4(A0, a_base + (((ks * 2 + acp) ^ arm) << 4));
            ldm4(A1, a_base + 16 * 256 + (((ks * 2 + acp) ^ arm) << 4));
#pragma unroll
            for (int nb = 0; nb < 4; ++nb) {
                uint32_t B[4];
                ldm4(B, b_base + nb * 16 * 256 + (((ks * 2 + bcp) ^ brm) << 4));
                mma16816(d[0][nb * 2 + 0], A0, B[0], B[1]);
                mma16816(d[0][nb * 2 + 1], A0, B[2], B[3]);
                mma16816(d[1][nb * 2 + 0], A1, B[0], B[1]);
                mma16816(d[1][nb * 2 + 1], A1, B[2], B[3]);
            }
        }

        // epilogue: MUFU activations, c update, h sum, h -> other A buffer
#pragma unroll
        for (int mt = 0; mt < 2; ++mt) {
#pragma unroll
            for (int rw = 0; rw < 2; ++rw) {
                const int wordl = wm * 32 + mt * 16 + (lane >> 2) + rw * 8;
#pragma unroll
                for (int jh = 0; jh < 2; ++jh) {
                    float hv[2];
#pragma unroll
                    for (int rj = 0; rj < 2; ++rj) {
                        const int r = rw * 2 + rj;
                        const float gi = d[mt][0 + jh][r];
                        const float gf = d[mt][2 + jh][r];
                        const float gg = d[mt][4 + jh][r];
                        const float go = d[mt][6 + jh][r];
                        const int u = ((mt * 2 + rw) * 2 + jh) * 2 + rj;
                        const float cc = sig_m(gf) * c_st[u] + sig_m(gi) * tanh_m(gg);
                        c_st[u] = cc;
                        const float hh = sig_m(go) * tanh_m(cc);
                        hs_st[u] += hh;
                        hv[rj] = hh;
                    }
                    const int k0 = wj * 16 + jh * 8 + 2 * (lane & 3);
                    const int chunk = k0 >> 3;
                    const uint32_t off =
                        (uint32_t)(wordl * 256 + ((chunk ^ (wordl & 7)) << 4) + (k0 & 7) * 2);
                    *(__half2*)(smem + A_OFF + wbuf + off) = __floats2half2_rn(hv[0], hv[1]);
                }
            }
        }
        __syncthreads();
    }

#pragma unroll
    for (int mt = 0; mt < 2; ++mt)
#pragma unroll
        for (int rw = 0; rw < 2; ++rw) {
            const int wordl = wm * 32 + mt * 16 + (lane >> 2) + rw * 8;
#pragma unroll
            for (int jh = 0; jh < 2; ++jh)
#pragma unroll
                for (int rj = 0; rj < 2; ++rj) {
                    const int jg = wj * 16 + jh * 8 + 2 * (lane & 3) + rj;
                    const int u = ((mt * 2 + rw) * 2 + jh) * 2 + rj;
                    g_cf[(size_t)(w_base + wordl) * 256 + dir * 128 + jg] = hs_st[u];
                }
        }
}

// ---------------- tensor-core output GEMM (split fp16) ----------------
#define OG_WID 0
#define OG_AH  1024
#define OG_AL  9216
#define OG_WH  17408
#define OG_WL  82944
#define OG_SMEM (OG_WL + 65536)   // 148480

__global__ __launch_bounds__(512, 1) void outgemm_kernel(const int* __restrict__ word_ids,
                                                         const float* __restrict__ word_table,
                                                         const float* __restrict__ b_out,
                                                         float* __restrict__ out) {
    extern __shared__ char smem[];
    const uint32_t sb = smem_u32(smem);
    int* wid_s = (int*)(smem + OG_WID);

    const int tid = threadIdx.x, wid = tid >> 5, lane = tid & 31;
    const int w_base = blockIdx.x * 64;
    const int wm = wid >> 3, wn = wid & 7;

    if (tid < 64) wid_s[tid] = word_ids[w_base + tid];
    __syncthreads();

    const int asub = lane >> 3;
    const int arow0 = wm * 32 + ((asub & 1) << 3) + (lane & 7);
    const int acp = asub >> 1;
    const int arm = arow0 & 7;
    const uint32_t ah_base = sb + OG_AH + arow0 * 128;
    const uint32_t al_base = sb + OG_AL + arow0 * 128;

    const int brow0 = wn * 64 + ((lane >> 4) << 3) + (lane & 7);
    const int bcp = (lane >> 3) & 1;
    const int brm = brow0 & 7;
    const uint32_t bh_base = sb + OG_WH + brow0 * 128;
    const uint32_t bl_base = sb + OG_WL + brow0 * 128;

    float d[2][8][4];
#pragma unroll
    for (int mt = 0; mt < 2; ++mt)
#pragma unroll
        for (int nt = 0; nt < 8; ++nt)
#pragma unroll
            for (int r = 0; r < 4; ++r) d[mt][nt][r] = 0.f;

    const int sm = tid >> 3;
    const int sk0 = (tid & 7) * 8;
    const int swid = wid_s[sm];
    const uint32_t soff = (uint32_t)(sm * 128 + (((sk0 >> 3) ^ (sm & 7)) << 4));

#pragma unroll 1
    for (int kc = 0; kc < 9; ++kc) {
        __syncthreads();
        {
            float f[8];
#pragma unroll
            for (int i = 0; i < 8; ++i) {
                const int kk = kc * 64 + sk0 + i;
                float v;
                if (kk < WDIM) v = word_table[(size_t)swid * WDIM + kk];
                else if (kk < KREAL) v = g_cf[(size_t)(w_base + sm) * 256 + (kk - WDIM)];
                else v = 0.0f;
                f[i] = v;
            }
            __half hh[8], hl[8];
#pragma unroll
            for (int i = 0; i < 8; ++i) {
                hh[i] = __float2half(f[i]);
                hl[i] = __float2half(f[i] - __half2float(hh[i]));
            }
            uint4 uh, ul;
            __half2 p0 = __halves2half2(hh[0], hh[1]), p1 = __halves2half2(hh[2], hh[3]);
            __half2 p2 = __halves2half2(hh[4], hh[5]), p3 = __halves2half2(hh[6], hh[7]);
            uh.x = *(uint32_t*)&p0; uh.y = *(uint32_t*)&p1;
            uh.z = *(uint32_t*)&p2; uh.w = *(uint32_t*)&p3;
            __half2 q0 = __halves2half2(hl[0], hl[1]), q1 = __halves2half2(hl[2], hl[3]);
            __half2 q2 = __halves2half2(hl[4], hl[5]), q3 = __halves2half2(hl[6], hl[7]);
            ul.x = *(uint32_t*)&q0; ul.y = *(uint32_t*)&q1;
            ul.z = *(uint32_t*)&q2; ul.w = *(uint32_t*)&q3;
            *(uint4*)(smem + OG_AH + soff) = uh;
            *(uint4*)(smem + OG_AL + soff) = ul;
        }
        {
            const float4* srch = (const float4*)((const char*)g_Wh + kc * 65536);
            const float4* srcl = (const float4*)((const char*)g_Wl + kc * 65536);
            float4* dsth = (float4*)(smem + OG_WH);
            float4* dstl = (float4*)(smem + OG_WL);
#pragma unroll
            for (int i = 0; i < 8; ++i) {
                dsth[tid + i * 512] = srch[tid + i * 512];
                dstl[tid + i * 512] = srcl[tid + i * 512];
            }
        }
        __syncthreads();

#pragma unroll
        for (int ks = 0; ks < 4; ++ks) {
            const uint32_t aoff = (uint32_t)(((ks * 2 + acp) ^ arm) << 4);
            const uint32_t boff = (uint32_t)(((ks * 2 + bcp) ^ brm) << 4);
            uint32_t Ah0[4], Ah1[4], Al0[4], Al1[4];
            ldm4(Ah0, ah_base + aoff);
            ldm4(Ah1, ah_base + 16 * 128 + aoff);
            ldm4(Al0, al_base + aoff);
            ldm4(Al1, al_base + 16 * 128 + aoff);
#pragma unroll
            for (int nb = 0; nb < 4; ++nb) {
                uint32_t Bh[4], Bl[4];
                ldm4(Bh, bh_base + nb * 16 * 128 + boff);
                ldm4(Bl, bl_base + nb * 16 * 128 + boff);
                mma16816(d[0][nb * 2 + 0], Ah0, Bh[0], Bh[1]);
                mma16816(d[0][nb * 2 + 1], Ah0, Bh[2], Bh[3]);
                mma16816(d[1][nb * 2 + 0], Ah1, Bh[0], Bh[1]);
                mma16816(d[1][nb * 2 + 1], Ah1, Bh[2], Bh[3]);
                mma16816(d[0][nb * 2 + 0], Ah0, Bl[0], Bl[1]);
                mma16816(d[0][nb * 2 + 1], Ah0, Bl[2], Bl[3]);
                mma16816(d[1][nb * 2 + 0], Ah1, Bl[0], Bl[1]);
                mma16816(d[1][nb * 2 + 1], Ah1, Bl[2], Bl[3]);
                mma16816(d[0][nb * 2 + 0], Al0, Bh[0], Bh[1]);
                mma16816(d[0][nb * 2 + 1], Al0, Bh[2], Bh[3]);
                mma16816(d[1][nb * 2 + 0], Al1, Bh[0], Bh[1]);
                mma16816(d[1][nb * 2 + 1], Al1, Bh[2], Bh[3]);
            }
        }
    }

#pragma unroll
    for (int mt = 0; mt < 2; ++mt)
#pragma unroll
        for (int rw = 0; rw < 2; ++rw) {
            const int wordl = wm * 32 + mt * 16 + (lane >> 2) + rw * 8;
            const size_t row = (size_t)(w_base + wordl) * ODIM;
#pragma unroll
            for (int nt = 0; nt < 8; ++nt) {
                const int n0 = wn * 64 + nt * 8 + 2 * (lane & 3);
                float2 r;
                r.x = tanhf_fast(d[mt][nt][rw * 2 + 0] + b_out[n0]);
                r.y = tanhf_fast(d[mt][nt][rw * 2 + 1] + b_out[n0 + 1]);
                *(float2*)&out[row + n0] = r;
            }
        }
}

// ---------------- launch ----------------
extern "C" void kernel_launch(void* const* d_in, const int* in_sizes, int n_in,
                              void* d_out, int out_size) {
    const int* word_ids     = (const int*)d_in[0];
    const int* char_ids     = (const int*)d_in[1];
    const float* word_table = (const float*)d_in[2];
    const float* char_table = (const float*)d_in[3];
    const float* Wih_f = (const float*)d_in[4];
    const float* Whh_f = (const float*)d_in[5];
    const float* bih_f = (const float*)d_in[6];
    const float* bhh_f = (const float*)d_in[7];
    const float* Wih_b = (const float*)d_in[8];
    const float* Whh_b = (const float*)d_in[9];
    const float* bih_b = (const float*)d_in[10];
    const float* bhh_b = (const float*)d_in[11];
    const float* W_out = (const float*)d_in[12];
    const float* b_out = (const float*)d_in[13];
    float* out = (float*)d_out;

    cudaFuncSetAttribute(lstm_kernel, cudaFuncAttributeMaxDynamicSharedMemorySize, LSTM_SMEM);
    cudaFuncSetAttribute(outgemm_kernel, cudaFuncAttributeMaxDynamicSharedMemorySize, OG_SMEM);

    prep_P<<<dim3(128, 2), 512>>>(char_table, Wih_f, bih_f, bhh_f, Wih_b, bih_b, bhh_b);
    prep_B<<<512, 256>>>(Whh_f, Whh_b);
    prep_Wsplit<<<1152, 256>>>(W_out);
    lstm_kernel<<<dim3(128, 2), 512, LSTM_SMEM>>>(char_ids);
    outgemm_kernel<<<128, 512, OG_SMEM>>>(word_ids, word_table, b_out, out);
}

// round 8
// speedup vs baseline: 7.3647x; 1.0129x over previous
#include <cuda_runtime.h>
#include <cuda_fp16.h>
#include <cstdint>

#define NW    8192
#define CL    16
#define CHID  128
#define GATES 512
#define CDIM  64
#define WDIM  300
#define ODIM  512
#define KREAL 556

// ---------------- device scratch ----------------
__device__ __align__(16) float  g_P[2 * 128 * GATES];   // preproj [dir][ch][j*4+ty], bias folded
__device__ __align__(16) __half g_B[2][GATES * CHID];   // Whh fp16, row-permuted + XOR8 swizzle
__device__ __align__(16) __half g_Wh[9 * 512 * 64];     // W_out hi fp16, 9 chunks, swizzled
__device__ __align__(16) __half g_Wl[9 * 512 * 64];     // W_out lo fp16
__device__ __align__(16) float  g_cf[NW * 256];

// ---------------- helpers ----------------
__device__ __forceinline__ uint32_t smem_u32(const void* p) {
    uint32_t a;
    asm("{ .reg .u64 t; cvta.to.shared.u64 t, %1; cvt.u32.u64 %0, t; }" : "=r"(a) : "l"(p));
    return a;
}
__device__ __forceinline__ float tanh_m(float x) {
    float y;
    asm("tanh.approx.f32 %0, %1;" : "=f"(y) : "f"(x));
    return y;
}
__device__ __forceinline__ float sig_m(float x) {
    return fmaf(0.5f, tanh_m(0.5f * x), 0.5f);
}
__device__ __forceinline__ float tanhf_fast(float x) {
    return 2.0f * __fdividef(1.0f, 1.0f + __expf(-2.0f * x)) - 1.0f;
}
__device__ __forceinline__ void ldm4(uint32_t* r, uint32_t addr) {
    asm volatile("ldmatrix.sync.aligned.m8n8.x4.shared.b16 {%0,%1,%2,%3}, [%4];"
                 : "=r"(r[0]), "=r"(r[1]), "=r"(r[2]), "=r"(r[3]) : "r"(addr));
}
__device__ __forceinline__ void mma16816(float* d, const uint32_t* a, uint32_t b0, uint32_t b1) {
    asm volatile("mma.sync.aligned.m16n8k16.row.col.f32.f16.f16.f32 "
                 "{%0,%1,%2,%3}, {%4,%5,%6,%7}, {%8,%9}, {%0,%1,%2,%3};"
                 : "+f"(d[0]), "+f"(d[1]), "+f"(d[2]), "+f"(d[3])
                 : "r"(a[0]), "r"(a[1]), "r"(a[2]), "r"(a[3]), "r"(b0), "r"(b1));
}
__device__ __forceinline__ void bar_half(int id) {
    asm volatile("bar.sync %0, 256;" :: "r"(id) : "memory");
}

// ---------------- combined prep kernel ----------------
// blocks [0,256): P table; [256,512): Whh fp16 swizzle; [512,1088): W_out split fp16
__global__ void prep_all(const float* __restrict__ ct,
                         const float* __restrict__ Wf, const float* __restrict__ bif,
                         const float* __restrict__ bhf,
                         const float* __restrict__ Wb, const float* __restrict__ bib,
                         const float* __restrict__ bhb,
                         const float* __restrict__ Whh_f, const float* __restrict__ Whh_b,
                         const float* __restrict__ W_out) {
    const int b = blockIdx.x, tid = threadIdx.x;
    if (b < 256) {
        // P[dir][ch][j*4+ty] = char_table[ch] . Wih[ty*128+j] + bih + bhh
        const int dir = b >> 7, ch = b & 127, n = tid;
        const float* W  = dir ? Wb : Wf;
        const float* bi = dir ? bib : bif;
        const float* bh = dir ? bhb : bhf;
        __shared__ float cs[CDIM];
        if (n < CDIM) cs[n] = ct[ch * CDIM + n];
        __syncthreads();
        int j = n >> 2, ty = n & 3, r = ty * CHID + j;
        float s = bi[r] + bh[r];
        const float* wr = W + r * CDIM;
#pragma unroll
        for (int d0 = 0; d0 < CDIM; ++d0) s += cs[d0] * wr[d0];
        g_P[(((dir << 7) + ch) << 9) + n] = s;
    } else if (b < 512) {
        // Whh -> fp16, row rr = (j>>4)*64 + ty*16 + (j&15), XOR8 swizzle (256B rows)
        int idx = (b - 256) * 512 + tid;  // 131072
        int dir = idx >> 16;
        int rem = idx & 65535;
        int r0 = rem >> 7, k = rem & 127;
        int ty = r0 >> 7, j = r0 & 127;
        const float* W = dir ? Whh_b : Whh_f;
        float v = W[r0 * CHID + k];
        int rr = ((j >> 4) << 6) + (ty << 4) + (j & 15);
        int chunk = k >> 3;
        uint32_t off = (uint32_t)(rr * 256 + ((chunk ^ (rr & 7)) << 4) + (k & 7) * 2);
        *(__half*)((char*)g_B[dir] + off) = __float2half(v);
    } else {
        // W_out split fp16 hi/lo, 9 K-chunks of 64, 128B rows, XOR8 swizzle
        int idx = (b - 512) * 512 + tid;  // 294912
        int kc = idx >> 15;
        int n = (idx >> 6) & 511;
        int k = idx & 63;
        int kk = kc * 64 + k;
        float v = (kk < KREAL) ? W_out[n * KREAL + kk] : 0.0f;
        __half hi = __float2half(v);
        __half lo = __float2half(v - __half2float(hi));
        uint32_t off = (uint32_t)(kc * 65536 + n * 128 + (((k >> 3) ^ (n & 7)) << 4) + (k & 7) * 2);
        *(__half*)((char*)g_Wh + off) = hi;
        *(__half*)((char*)g_Wl + off) = lo;
    }
}

// ---------------- HMMA bidirectional char-LSTM ----------------
// grid (128,2): 64 words/CTA, 1 dir. 16 warps in 2 INDEPENDENT 8-warp halves (wm),
// each half syncs via its own named barrier -> halves drift and overlap phases.
#define CI_OFF 0
#define A_OFF  4096          // 2 buffers x 16384
#define B_OFF  36864
#define LSTM_SMEM (B_OFF + 131072)   // 167936

__global__ __launch_bounds__(512, 1) void lstm_kernel(const int* __restrict__ char_ids) {
    extern __shared__ char smem[];
    const uint32_t sb = smem_u32(smem);
    int* ci_s = (int*)(smem + CI_OFF);

    const int tid = threadIdx.x, wid = tid >> 5, lane = tid & 31;
    const int dir = blockIdx.y;
    const int w_base = blockIdx.x * 64;
    const int wm = wid >> 3, wj = wid & 7;

    {
        const int* src = char_ids + (size_t)w_base * CL;
        ci_s[tid] = src[tid];
        ci_s[tid + 512] = src[tid + 512];
        float4* az = (float4*)(smem + A_OFF);
        az[tid] = make_float4(0.f, 0.f, 0.f, 0.f);
        az[tid + 512] = make_float4(0.f, 0.f, 0.f, 0.f);
        const float4* bsrc = (const float4*)g_B[dir];
        float4* bdst = (float4*)(smem + B_OFF);
#pragma unroll
        for (int i = 0; i < 16; ++i) bdst[tid + i * 512] = bsrc[tid + i * 512];
    }
    __syncthreads();

    const int asub = lane >> 3;
    const int arow0 = wm * 32 + ((asub & 1) << 3) + (lane & 7);
    const int acp = asub >> 1;
    const int arm = arow0 & 7;

    const int brow0 = wj * 64 + ((lane >> 4) << 3) + (lane & 7);
    const int bcp = (lane >> 3) & 1;
    const int brm = brow0 & 7;
    const uint32_t b_base = sb + B_OFF + brow0 * 256;

    const int mybar = 1 + wm;   // named barrier per half

    float d[2][8][4];
    float c_st[16], hs_st[16];
#pragma unroll
    for (int u = 0; u < 16; ++u) { c_st[u] = 0.f; hs_st[u] = 0.f; }

#pragma unroll 1
    for (int ti = 0; ti < CL; ++ti) {
        const int t = dir ? (CL - 1 - ti) : ti;
        const uint32_t rbuf = (uint32_t)(ti & 1) << 14;
        const uint32_t wbuf = rbuf ^ 16384u;
        const uint32_t a_base = sb + A_OFF + rbuf + arow0 * 256;

        // init accumulators from P (L2 loads overlap with tensor work)
#pragma unroll
        for (int mt = 0; mt < 2; ++mt)
#pragma unroll
            for (int rw = 0; rw < 2; ++rw) {
                const int wordl = wm * 32 + mt * 16 + (lane >> 2) + rw * 8;
                const int ch = ci_s[wordl * CL + t];
                const float4* Pf = (const float4*)(g_P + (((dir << 7) + ch) << 9));
#pragma unroll
                for (int jh = 0; jh < 2; ++jh)
#pragma unroll
                    for (int rj = 0; rj < 2; ++rj) {
                        const int jg = wj * 16 + jh * 8 + 2 * (lane & 3) + rj;
                        const float4 p = Pf[jg];
                        const int r = rw * 2 + rj;
                        d[mt][0 + jh][r] = p.x;
                        d[mt][2 + jh][r] = p.y;
                        d[mt][4 + jh][r] = p.z;
                        d[mt][6 + jh][r] = p.w;
                    }
            }

        // gates += h(t-1) @ Whh^T
#pragma unroll
        for (int ks = 0; ks < 8; ++ks) {
            uint32_t A0[4], A1[4];
            ldm4(A0, a_base + (((ks * 2 + acp) ^ arm) << 4));
            ldm4(A1, a_base + 16 * 256 + (((ks * 2 + acp) ^ arm) << 4));
#pragma unroll
            for (int nb = 0; nb < 4; ++nb) {
                uint32_t B[4];
                ldm4(B, b_base + nb * 16 * 256 + (((ks * 2 + bcp) ^ brm) << 4));
                mma16816(d[0][nb * 2 + 0], A0, B[0], B[1]);
                mma16816(d[0][nb * 2 + 1], A0, B[2], B[3]);
                mma16816(d[1][nb * 2 + 0], A1, B[0], B[1]);
                mma16816(d[1][nb * 2 + 1], A1, B[2], B[3]);
            }
        }

        // epilogue: MUFU activations, c update, h sum, h -> other A buffer
#pragma unroll
        for (int mt = 0; mt < 2; ++mt) {
#pragma unroll
            for (int rw = 0; rw < 2; ++rw) {
                const int wordl = wm * 32 + mt * 16 + (lane >> 2) + rw * 8;
#pragma unroll
                for (int jh = 0; jh < 2; ++jh) {
                    float hv[2];
#pragma unroll
                    for (int rj = 0; rj < 2; ++rj) {
                        const int r = rw * 2 + rj;
                        const float gi = d[mt][0 + jh][r];
                        const float gf = d[mt][2 + jh][r];
                        const float gg = d[mt][4 + jh][r];
                        const float go = d[mt][6 + jh][r];
                        const int u = ((mt * 2 + rw) * 2 + jh) * 2 + rj;
                        const float cc = sig_m(gf) * c_st[u] + sig_m(gi) * tanh_m(gg);
                        c_st[u] = cc;
                        const float hh = sig_m(go) * tanh_m(cc);
                        hs_st[u] += hh;
                        hv[rj] = hh;
                    }
                    const int k0 = wj * 16 + jh * 8 + 2 * (lane & 3);
                    const int chunk = k0 >> 3;
                    const uint32_t off =
                        (uint32_t)(wordl * 256 + ((chunk ^ (wordl & 7)) << 4) + (k0 & 7) * 2);
                    *(__half2*)(smem + A_OFF + wbuf + off) = __floats2half2_rn(hv[0], hv[1]);
                }
            }
        }
        bar_half(mybar);   // only this half's 8 warps
    }

#pragma unroll
    for (int mt = 0; mt < 2; ++mt)
#pragma unroll
        for (int rw = 0; rw < 2; ++rw) {
            const int wordl = wm * 32 + mt * 16 + (lane >> 2) + rw * 8;
#pragma unroll
            for (int jh = 0; jh < 2; ++jh)
#pragma unroll
                for (int rj = 0; rj < 2; ++rj) {
                    const int jg = wj * 16 + jh * 8 + 2 * (lane & 3) + rj;
                    const int u = ((mt * 2 + rw) * 2 + jh) * 2 + rj;
                    g_cf[(size_t)(w_base + wordl) * 256 + dir * 128 + jg] = hs_st[u];
                }
        }
}

// ---------------- tensor-core output GEMM (split fp16) ----------------
#define OG_WID 0
#define OG_AH  1024
#define OG_AL  9216
#define OG_WH  17408
#define OG_WL  82944
#define OG_SMEM (OG_WL + 65536)   // 148480

__global__ __launch_bounds__(512, 1) void outgemm_kernel(const int* __restrict__ word_ids,
                                                         const float* __restrict__ word_table,
                                                         const float* __restrict__ b_out,
                                                         float* __restrict__ out) {
    extern __shared__ char smem[];
    const uint32_t sb = smem_u32(smem);
    int* wid_s = (int*)(smem + OG_WID);

    const int tid = threadIdx.x, wid = tid >> 5, lane = tid & 31;
    const int w_base = blockIdx.x * 64;
    const int wm = wid >> 3, wn = wid & 7;

    if (tid < 64) wid_s[tid] = word_ids[w_base + tid];
    __syncthreads();

    const int asub = lane >> 3;
    const int arow0 = wm * 32 + ((asub & 1) << 3) + (lane & 7);
    const int acp = asub >> 1;
    const int arm = arow0 & 7;
    const uint32_t ah_base = sb + OG_AH + arow0 * 128;
    const uint32_t al_base = sb + OG_AL + arow0 * 128;

    const int brow0 = wn * 64 + ((lane >> 4) << 3) + (lane & 7);
    const int bcp = (lane >> 3) & 1;
    const int brm = brow0 & 7;
    const uint32_t bh_base = sb + OG_WH + brow0 * 128;
    const uint32_t bl_base = sb + OG_WL + brow0 * 128;

    float d[2][8][4];
#pragma unroll
    for (int mt = 0; mt < 2; ++mt)
#pragma unroll
        for (int nt = 0; nt < 8; ++nt)
#pragma unroll
            for (int r = 0; r < 4; ++r) d[mt][nt][r] = 0.f;

    const int sm = tid >> 3;
    const int sk0 = (tid & 7) * 8;
    const int swid = wid_s[sm];
    const uint32_t soff = (uint32_t)(sm * 128 + (((sk0 >> 3) ^ (sm & 7)) << 4));

#pragma unroll 1
    for (int kc = 0; kc < 9; ++kc) {
        __syncthreads();
        {
            float f[8];
#pragma unroll
            for (int i = 0; i < 8; ++i) {
                const int kk = kc * 64 + sk0 + i;
                float v;
                if (kk < WDIM) v = word_table[(size_t)swid * WDIM + kk];
                else if (kk < KREAL) v = g_cf[(size_t)(w_base + sm) * 256 + (kk - WDIM)];
                else v = 0.0f;
                f[i] = v;
            }
            __half hh[8], hl[8];
#pragma unroll
            for (int i = 0; i < 8; ++i) {
                hh[i] = __float2half(f[i]);
                hl[i] = __float2half(f[i] - __half2float(hh[i]));
            }
            uint4 uh, ul;
            __half2 p0 = __halves2half2(hh[0], hh[1]), p1 = __halves2half2(hh[2], hh[3]);
            __half2 p2 = __halves2half2(hh[4], hh[5]), p3 = __halves2half2(hh[6], hh[7]);
            uh.x = *(uint32_t*)&p0; uh.y = *(uint32_t*)&p1;
            uh.z = *(uint32_t*)&p2; uh.w = *(uint32_t*)&p3;
            __half2 q0 = __halves2half2(hl[0], hl[1]), q1 = __halves2half2(hl[2], hl[3]);
            __half2 q2 = __halves2half2(hl[4], hl[5]), q3 = __halves2half2(hl[6], hl[7]);
            ul.x = *(uint32_t*)&q0; ul.y = *(uint32_t*)&q1;
            ul.z = *(uint32_t*)&q2; ul.w = *(uint32_t*)&q3;
            *(uint4*)(smem + OG_AH + soff) = uh;
            *(uint4*)(smem + OG_AL + soff) = ul;
        }
        {
            const float4* srch = (const float4*)((const char*)g_Wh + kc * 65536);
            const float4* srcl = (const float4*)((const char*)g_Wl + kc * 65536);
            float4* dsth = (float4*)(smem + OG_WH);
            float4* dstl = (float4*)(smem + OG_WL);
#pragma unroll
            for (int i = 0; i < 8; ++i) {
                dsth[tid + i * 512] = srch[tid + i * 512];
                dstl[tid + i * 512] = srcl[tid + i * 512];
            }
        }
        __syncthreads();

#pragma unroll
        for (int ks = 0; ks < 4; ++ks) {
            const uint32_t aoff = (uint32_t)(((ks * 2 + acp) ^ arm) << 4);
            const uint32_t boff = (uint32_t)(((ks * 2 + bcp) ^ brm) << 4);
            uint32_t Ah0[4], Ah1[4], Al0[4], Al1[4];
            ldm4(Ah0, ah_base + aoff);
            ldm4(Ah1, ah_base + 16 * 128 + aoff);
            ldm4(Al0, al_base + aoff);
            ldm4(Al1, al_base + 16 * 128 + aoff);
#pragma unroll
            for (int nb = 0; nb < 4; ++nb) {
                uint32_t Bh[4], Bl[4];
                ldm4(Bh, bh_base + nb * 16 * 128 + boff);
                ldm4(Bl, bl_base + nb * 16 * 128 + boff);
                mma16816(d[0][nb * 2 + 0], Ah0, Bh[0], Bh[1]);
                mma16816(d[0][nb * 2 + 1], Ah0, Bh[2], Bh[3]);
                mma16816(d[1][nb * 2 + 0], Ah1, Bh[0], Bh[1]);
                mma16816(d[1][nb * 2 + 1], Ah1, Bh[2], Bh[3]);
                mma16816(d[0][nb * 2 + 0], Ah0, Bl[0], Bl[1]);
                mma16816(d[0][nb * 2 + 1], Ah0, Bl[2], Bl[3]);
                mma16816(d[1][nb * 2 + 0], Ah1, Bl[0], Bl[1]);
                mma16816(d[1][nb * 2 + 1], Ah1, Bl[2], Bl[3]);
                mma16816(d[0][nb * 2 + 0], Al0, Bh[0], Bh[1]);
                mma16816(d[0][nb * 2 + 1], Al0, Bh[2], Bh[3]);
                mma16816(d[1][nb * 2 + 0], Al1, Bh[0], Bh[1]);
                mma16816(d[1][nb * 2 + 1], Al1, Bh[2], Bh[3]);
            }
        }
    }

#pragma unroll
    for (int mt = 0; mt < 2; ++mt)
#pragma unroll
        for (int rw = 0; rw < 2; ++rw) {
            const int wordl = wm * 32 + mt * 16 + (lane >> 2) + rw * 8;
            const size_t row = (size_t)(w_base + wordl) * ODIM;
#pragma unroll
            for (int nt = 0; nt < 8; ++nt) {
                const int n0 = wn * 64 + nt * 8 + 2 * (lane & 3);
                float2 r;
                r.x = tanhf_fast(d[mt][nt][rw * 2 + 0] + b_out[n0]);
                r.y = tanhf_fast(d[mt][nt][rw * 2 + 1] + b_out[n0 + 1]);
                *(float2*)&out[row + n0] = r;
            }
        }
}

// ---------------- launch ----------------
extern "C" void kernel_launch(void* const* d_in, const int* in_sizes, int n_in,
                              void* d_out, int out_size) {
    const int* word_ids     = (const int*)d_in[0];
    const int* char_ids     = (const int*)d_in[1];
    const float* word_table = (const float*)d_in[2];
    const float* char_table = (const float*)d_in[3];
    const float* Wih_f = (const float*)d_in[4];
    const float* Whh_f = (const float*)d_in[5];
    const float* bih_f = (const float*)d_in[6];
    const float* bhh_f = (const float*)d_in[7];
    const float* Wih_b = (const float*)d_in[8];
    const float* Whh_b = (const float*)d_in[9];
    const float* bih_b = (const float*)d_in[10];
    const float* bhh_b = (const float*)d_in[11];
    const float* W_out = (const float*)d_in[12];
    const float* b_out = (const float*)d_in[13];
    float* out = (float*)d_out;

    cudaFuncSetAttribute(lstm_kernel, cudaFuncAttributeMaxDynamicSharedMemorySize, LSTM_SMEM);
    cudaFuncSetAttribute(outgemm_kernel, cudaFuncAttributeMaxDynamicSharedMemorySize, OG_SMEM);

    prep_all<<<1088, 512>>>(char_table, Wih_f, bih_f, bhh_f, Wih_b, bih_b, bhh_b,
                            Whh_f, Whh_b, W_out);
    lstm_kernel<<<dim3(128, 2), 512, LSTM_SMEM>>>(char_ids);
    outgemm_kernel<<<128, 512, OG_SMEM>>>(word_ids, word_table, b_out, out);
}

// round 9
// speedup vs baseline: 8.9016x; 1.2087x over previous
#include <cuda_runtime.h>
#include <cuda_fp16.h>
#include <cstdint>

#define NW    8192
#define CL    16
#define CHID  128
#define GATES 512
#define CDIM  64
#define WDIM  300
#define ODIM  512
#define KREAL 556

// ---------------- device scratch ----------------
__device__ __align__(16) __half g_P16[2 * 128 * GATES];  // preproj fp16 [dir][ch][n=4j+ty], bias folded
__device__ __align__(16) __half g_B[2][GATES * CHID];    // Whh fp16, row-permuted + XOR8 swizzle
__device__ __align__(16) __half g_Wh[9 * 512 * 64];      // W_out hi fp16, 9 chunks, swizzled
__device__ __align__(16) __half g_Wl[9 * 512 * 64];      // W_out lo fp16
__device__ __align__(16) float  g_cf[NW * 256];

// ---------------- helpers ----------------
__device__ __forceinline__ uint32_t smem_u32(const void* p) {
    uint32_t a;
    asm("{ .reg .u64 t; cvta.to.shared.u64 t, %1; cvt.u32.u64 %0, t; }" : "=r"(a) : "l"(p));
    return a;
}
__device__ __forceinline__ float tanh_m(float x) {
    float y;
    asm("tanh.approx.f32 %0, %1;" : "=f"(y) : "f"(x));
    return y;
}
__device__ __forceinline__ float sig_m(float x) {
    return fmaf(0.5f, tanh_m(0.5f * x), 0.5f);
}
__device__ __forceinline__ float tanhf_fast(float x) {
    return 2.0f * __fdividef(1.0f, 1.0f + __expf(-2.0f * x)) - 1.0f;
}
__device__ __forceinline__ void ldm4(uint32_t* r, uint32_t addr) {
    asm volatile("ldmatrix.sync.aligned.m8n8.x4.shared.b16 {%0,%1,%2,%3}, [%4];"
                 : "=r"(r[0]), "=r"(r[1]), "=r"(r[2]), "=r"(r[3]) : "r"(addr));
}
__device__ __forceinline__ void mma16816(float* d, const uint32_t* a, uint32_t b0, uint32_t b1) {
    asm volatile("mma.sync.aligned.m16n8k16.row.col.f32.f16.f16.f32 "
                 "{%0,%1,%2,%3}, {%4,%5,%6,%7}, {%8,%9}, {%0,%1,%2,%3};"
                 : "+f"(d[0]), "+f"(d[1]), "+f"(d[2]), "+f"(d[3])
                 : "r"(a[0]), "r"(a[1]), "r"(a[2]), "r"(a[3]), "r"(b0), "r"(b1));
}
__device__ __forceinline__ void bar_half(int id) {
    asm volatile("bar.sync %0, 256;" :: "r"(id) : "memory");
}
__device__ __forceinline__ void cp16(uint32_t dst, const void* src) {
    asm volatile("cp.async.cg.shared.global [%0], [%1], 16;" :: "r"(dst), "l"(src) : "memory");
}
__device__ __forceinline__ void cp_commit() {
    asm volatile("cp.async.commit_group;" ::: "memory");
}
__device__ __forceinline__ void cp_wait0() {
    asm volatile("cp.async.wait_group 0;" ::: "memory");
}
__device__ __forceinline__ void lds128(uint32_t* q, uint32_t addr) {
    asm volatile("ld.shared.v4.b32 {%0,%1,%2,%3}, [%4];"
                 : "=r"(q[0]), "=r"(q[1]), "=r"(q[2]), "=r"(q[3]) : "r"(addr));
}

// ---------------- combined prep kernel (coalesced) ----------------
// blocks [0,256): P16 table; [256,288): Whh fp16 swizzle; [288,360): W_out split fp16
__global__ void prep_all(const float* __restrict__ ct,
                         const float* __restrict__ Wf, const float* __restrict__ bif,
                         const float* __restrict__ bhf,
                         const float* __restrict__ Wb, const float* __restrict__ bib,
                         const float* __restrict__ bhb,
                         const float* __restrict__ Whh_f, const float* __restrict__ Whh_b,
                         const float* __restrict__ W_out) {
    const int b = blockIdx.x, tid = threadIdx.x;
    __shared__ float cs[CDIM];
    if (b < 256) {
        // P16[dir][ch][n=4j+ty] = char_table[ch].Wih[ty*128+j] + bih + bhh (fp16)
        const int dir = b >> 7, ch = b & 127;
        const int wrp = tid >> 5, lane = tid & 31;
        const float* W  = dir ? Wb : Wf;
        const float* bi = dir ? bib : bif;
        const float* bh = dir ? bhb : bhf;
        if (tid < CDIM) cs[tid] = ct[ch * CDIM + tid];
        __syncthreads();
        const float c0 = cs[2 * lane], c1 = cs[2 * lane + 1];
        float keep = 0.f;
#pragma unroll 1
        for (int i = 0; i < 32; ++i) {
            const int n = wrp * 32 + i;
            const int j = n >> 2, ty = n & 3, r = ty * CHID + j;
            const float2 w2 = *(const float2*)&W[r * CDIM + 2 * lane];
            float s = w2.x * c0 + w2.y * c1;
#pragma unroll
            for (int o = 16; o > 0; o >>= 1)
                s += __shfl_xor_sync(0xFFFFFFFFu, s, o);
            if (lane == i) keep = s + bi[r] + bh[r];
        }
        g_P16[(((dir << 7) + ch) << 9) + wrp * 32 + lane] = __float2half(keep);
    } else if (b < 288) {
        // Whh -> fp16 swizzled layout, one 16B chunk per thread
        const int cid = (b - 256) * 512 + tid;        // 16384
        const int dir = cid >> 13;
        const int rem = cid & 8191;
        const int rr = rem >> 4, cs_w = rem & 15;
        const int chunk = cs_w ^ (rr & 7);
        const int k0 = chunk * 8;
        const int j = ((rr >> 6) << 4) | (rr & 15);
        const int ty = (rr >> 4) & 3;
        const int r0 = ty * CHID + j;
        const float* W = dir ? Whh_b : Whh_f;
        const float4 f0 = *(const float4*)&W[r0 * CHID + k0];
        const float4 f1 = *(const float4*)&W[r0 * CHID + k0 + 4];
        __half2 h0 = __floats2half2_rn(f0.x, f0.y), h1 = __floats2half2_rn(f0.z, f0.w);
        __half2 h2 = __floats2half2_rn(f1.x, f1.y), h3 = __floats2half2_rn(f1.z, f1.w);
        uint4 u;
        u.x = *(uint32_t*)&h0; u.y = *(uint32_t*)&h1;
        u.z = *(uint32_t*)&h2; u.w = *(uint32_t*)&h3;
        *(uint4*)((char*)g_B[dir] + rr * 256 + cs_w * 16) = u;
    } else {
        // W_out -> split hi/lo fp16, one 16B chunk per thread per table
        const int cid = (b - 288) * 512 + tid;        // 36864
        const int kc = cid / 4096;
        const int rem = cid & 4095;
        const int n = rem >> 3, cs_w = rem & 7;
        const int chunk = cs_w ^ (n & 7);
        const int k0 = chunk * 8;
        float f[8];
#pragma unroll
        for (int i = 0; i < 8; ++i) {
            const int kk = kc * 64 + k0 + i;
            f[i] = (kk < KREAL) ? W_out[n * KREAL + kk] : 0.0f;
        }
        __half hh[8], hl[8];
#pragma unroll
        for (int i = 0; i < 8; ++i) {
            hh[i] = __float2half(f[i]);
            hl[i] = __float2half(f[i] - __half2float(hh[i]));
        }
        uint4 uh, ul;
        __half2 p0 = __halves2half2(hh[0], hh[1]), p1 = __halves2half2(hh[2], hh[3]);
        __half2 p2 = __halves2half2(hh[4], hh[5]), p3 = __halves2half2(hh[6], hh[7]);
        uh.x = *(uint32_t*)&p0; uh.y = *(uint32_t*)&p1;
        uh.z = *(uint32_t*)&p2; uh.w = *(uint32_t*)&p3;
        __half2 q0 = __halves2half2(hl[0], hl[1]), q1 = __halves2half2(hl[2], hl[3]);
        __half2 q2 = __halves2half2(hl[4], hl[5]), q3 = __halves2half2(hl[6], hl[7]);
        ul.x = *(uint32_t*)&q0; ul.y = *(uint32_t*)&q1;
        ul.z = *(uint32_t*)&q2; ul.w = *(uint32_t*)&q3;
        const uint32_t off = (uint32_t)(kc * 65536 + n * 128 + cs_w * 16);
        *(uint4*)((char*)g_Wh + off) = uh;
        *(uint4*)((char*)g_Wl + off) = ul;
    }
}

// ---------------- HMMA bidirectional char-LSTM with cp.async P pipeline ----------------
// grid (128,2): 64 words/CTA, 1 dir. 2 independent 8-warp halves (named barriers).
// P(t+1) prefetched to smem (fp16, stride 1072B) during step t's tail; single A buffer.
#define CI_OFF 0
#define A_OFF  4096
#define B_OFF  20480
#define P_OFF  151552
#define P_STRIDE 1072
#define LSTM_SMEM (P_OFF + 64 * P_STRIDE)   // 220160

__global__ __launch_bounds__(512, 1) void lstm_kernel(const int* __restrict__ char_ids) {
    extern __shared__ char smem[];
    const uint32_t sb = smem_u32(smem);
    int* ci_s = (int*)(smem + CI_OFF);

    const int tid = threadIdx.x, wid = tid >> 5, lane = tid & 31;
    const int dir = blockIdx.y;
    const int w_base = blockIdx.x * 64;
    const int wm = wid >> 3, wj = wid & 7;

    {
        const int* src = char_ids + (size_t)w_base * CL;
        ci_s[tid] = src[tid];
        ci_s[tid + 512] = src[tid + 512];
        float4* az = (float4*)(smem + A_OFF);
        az[tid] = make_float4(0.f, 0.f, 0.f, 0.f);
        az[tid + 512] = make_float4(0.f, 0.f, 0.f, 0.f);
        const float4* bsrc = (const float4*)g_B[dir];
        float4* bdst = (float4*)(smem + B_OFF);
#pragma unroll
        for (int i = 0; i < 16; ++i) bdst[tid + i * 512] = bsrc[tid + i * 512];
    }
    __syncthreads();

    // P prefetch roles: word pw = tid>>3 (half-local: half 0 -> words 0..31), 8 chunks each
    const int pw = tid >> 3;
    const int pc0 = tid & 7;
    const uint32_t pdst0 = sb + P_OFF + pw * P_STRIDE;
    const char* psrc_dir = (const char*)g_P16 + ((size_t)dir << 17);  // dir*128*512*2

    // prologue: stage P(t0)
    {
        const int t0 = dir ? (CL - 1) : 0;
        const int ch = ci_s[pw * CL + t0];
        const char* srow = psrc_dir + ((size_t)ch << 10);
#pragma unroll
        for (int i = 0; i < 8; ++i) {
            const int c = pc0 + i * 8;
            cp16(pdst0 + c * 16, srow + c * 16);
        }
        cp_commit();
    }

    const int asub = lane >> 3;
    const int arow0 = wm * 32 + ((asub & 1) << 3) + (lane & 7);
    const int acp = asub >> 1;
    const int arm = arow0 & 7;
    const uint32_t a_base = sb + A_OFF + arow0 * 256;

    const int brow0 = wj * 64 + ((lane >> 4) << 3) + (lane & 7);
    const int bcp = (lane >> 3) & 1;
    const int brm = brow0 & 7;
    const uint32_t b_base = sb + B_OFF + brow0 * 256;

    const int mybar = 1 + wm;

    float d[2][8][4];
    float c_st[16], hs_st[16];
#pragma unroll
    for (int u = 0; u < 16; ++u) { c_st[u] = 0.f; hs_st[u] = 0.f; }

#pragma unroll 1
    for (int ti = 0; ti < CL; ++ti) {
        const int t = dir ? (CL - 1 - ti) : ti;

#pragma unroll
        for (int mt = 0; mt < 2; ++mt)
#pragma unroll
            for (int nt = 0; nt < 8; ++nt)
#pragma unroll
                for (int r = 0; r < 4; ++r) d[mt][nt][r] = 0.f;

        // gates = h(t-1) @ Whh^T
#pragma unroll
        for (int ks = 0; ks < 8; ++ks) {
            uint32_t A0[4], A1[4];
            ldm4(A0, a_base + (((ks * 2 + acp) ^ arm) << 4));
            ldm4(A1, a_base + 16 * 256 + (((ks * 2 + acp) ^ arm) << 4));
#pragma unroll
            for (int nb = 0; nb < 4; ++nb) {
                uint32_t B[4];
                ldm4(B, b_base + nb * 16 * 256 + (((ks * 2 + bcp) ^ brm) << 4));
                mma16816(d[0][nb * 2 + 0], A0, B[0], B[1]);
                mma16816(d[0][nb * 2 + 1], A0, B[2], B[3]);
                mma16816(d[1][nb * 2 + 0], A1, B[0], B[1]);
                mma16816(d[1][nb * 2 + 1], A1, B[2], B[3]);
            }
        }

        cp_wait0();        // own P(t) chunks done
        bar_half(mybar);   // A reads done; all half threads' P(t) visible

        // epilogue: d += P(t) (smem fp16), activations, c update, h sum, h(t) -> A
#pragma unroll
        for (int mt = 0; mt < 2; ++mt) {
#pragma unroll
            for (int rw = 0; rw < 2; ++rw) {
                const int wordl = wm * 32 + mt * 16 + (lane >> 2) + rw * 8;
#pragma unroll
                for (int jh = 0; jh < 2; ++jh) {
                    const int jg0 = wj * 16 + jh * 8 + 2 * (lane & 3);
                    uint32_t q[4];
                    lds128(q, sb + P_OFF + wordl * P_STRIDE + jg0 * 8);
                    float hv[2];
#pragma unroll
                    for (int rj = 0; rj < 2; ++rj) {
                        const float2 pa = __half22float2(*(__half2*)&q[rj * 2 + 0]);
                        const float2 pb = __half22float2(*(__half2*)&q[rj * 2 + 1]);
                        const int r = rw * 2 + rj;
                        const float gi = d[mt][0 + jh][r] + pa.x;
                        const float gf = d[mt][2 + jh][r] + pa.y;
                        const float gg = d[mt][4 + jh][r] + pb.x;
                        const float go = d[mt][6 + jh][r] + pb.y;
                        const int u = ((mt * 2 + rw) * 2 + jh) * 2 + rj;
                        const float cc = sig_m(gf) * c_st[u] + sig_m(gi) * tanh_m(gg);
                        c_st[u] = cc;
                        const float hh = sig_m(go) * tanh_m(cc);
                        hs_st[u] += hh;
                        hv[rj] = hh;
                    }
                    const int k0 = jg0 + jh * 0;  // k0 == jg0 base for this unit pair
                    const int kk0 = wj * 16 + jh * 8 + 2 * (lane & 3);
                    const int chunk = kk0 >> 3;
                    const uint32_t off =
                        (uint32_t)(wordl * 256 + ((chunk ^ (wordl & 7)) << 4) + (kk0 & 7) * 2);
                    *(__half2*)(smem + A_OFF + off) = __floats2half2_rn(hv[0], hv[1]);
                    (void)k0;
                }
            }
        }
        bar_half(mybar);   // P(t) reads + h(t) writes published within half

        // prefetch P(t+1) (overlaps next step's MMA phase)
        if (ti + 1 < CL) {
            const int tn = dir ? (t - 1) : (t + 1);
            const int ch = ci_s[pw * CL + tn];
            const char* srow = psrc_dir + ((size_t)ch << 10);
#pragma unroll
            for (int i = 0; i < 8; ++i) {
                const int c = pc0 + i * 8;
                cp16(pdst0 + c * 16, srow + c * 16);
            }
        }
        cp_commit();
    }

#pragma unroll
    for (int mt = 0; mt < 2; ++mt)
#pragma unroll
        for (int rw = 0; rw < 2; ++rw) {
            const int wordl = wm * 32 + mt * 16 + (lane >> 2) + rw * 8;
#pragma unroll
            for (int jh = 0; jh < 2; ++jh)
#pragma unroll
                for (int rj = 0; rj < 2; ++rj) {
                    const int jg = wj * 16 + jh * 8 + 2 * (lane & 3) + rj;
                    const int u = ((mt * 2 + rw) * 2 + jh) * 2 + rj;
                    g_cf[(size_t)(w_base + wordl) * 256 + dir * 128 + jg] = hs_st[u];
                }
        }
}

// ---------------- tensor-core output GEMM (split fp16) ----------------
#define OG_WID 0
#define OG_AH  1024
#define OG_AL  9216
#define OG_WH  17408
#define OG_WL  82944
#define OG_SMEM (OG_WL + 65536)   // 148480

__global__ __launch_bounds__(512, 1) void outgemm_kernel(const int* __restrict__ word_ids,
                                                         const float* __restrict__ word_table,
                                                         const float* __restrict__ b_out,
                                                         float* __restrict__ out) {
    extern __shared__ char smem[];
    const uint32_t sb = smem_u32(smem);
    int* wid_s = (int*)(smem + OG_WID);

    const int tid = threadIdx.x, wid = tid >> 5, lane = tid & 31;
    const int w_base = blockIdx.x * 64;
    const int wm = wid >> 3, wn = wid & 7;

    if (tid < 64) wid_s[tid] = word_ids[w_base + tid];
    __syncthreads();

    const int asub = lane >> 3;
    const int arow0 = wm * 32 + ((asub & 1) << 3) + (lane & 7);
    const int acp = asub >> 1;
    const int arm = arow0 & 7;
    const uint32_t ah_base = sb + OG_AH + arow0 * 128;
    const uint32_t al_base = sb + OG_AL + arow0 * 128;

    const int brow0 = wn * 64 + ((lane >> 4) << 3) + (lane & 7);
    const int bcp = (lane >> 3) & 1;
    const int brm = brow0 & 7;
    const uint32_t bh_base = sb + OG_WH + brow0 * 128;
    const uint32_t bl_base = sb + OG_WL + brow0 * 128;

    float d[2][8][4];
#pragma unroll
    for (int mt = 0; mt < 2; ++mt)
#pragma unroll
        for (int nt = 0; nt < 8; ++nt)
#pragma unroll
            for (int r = 0; r < 4; ++r) d[mt][nt][r] = 0.f;

    const int sm = tid >> 3;
    const int sk0 = (tid & 7) * 8;
    const int swid = wid_s[sm];
    const uint32_t soff = (uint32_t)(sm * 128 + (((sk0 >> 3) ^ (sm & 7)) << 4));

#pragma unroll 1
    for (int kc = 0; kc < 9; ++kc) {
        __syncthreads();
        {
            float f[8];
#pragma unroll
            for (int i = 0; i < 8; ++i) {
                const int kk = kc * 64 + sk0 + i;
                float v;
                if (kk < WDIM) v = word_table[(size_t)swid * WDIM + kk];
                else if (kk < KREAL) v = g_cf[(size_t)(w_base + sm) * 256 + (kk - WDIM)];
                else v = 0.0f;
                f[i] = v;
            }
            __half hh[8], hl[8];
#pragma unroll
            for (int i = 0; i < 8; ++i) {
                hh[i] = __float2half(f[i]);
                hl[i] = __float2half(f[i] - __half2float(hh[i]));
            }
            uint4 uh, ul;
            __half2 p0 = __halves2half2(hh[0], hh[1]), p1 = __halves2half2(hh[2], hh[3]);
            __half2 p2 = __halves2half2(hh[4], hh[5]), p3 = __halves2half2(hh[6], hh[7]);
            uh.x = *(uint32_t*)&p0; uh.y = *(uint32_t*)&p1;
            uh.z = *(uint32_t*)&p2; uh.w = *(uint32_t*)&p3;
            __half2 q0 = __halves2half2(hl[0], hl[1]), q1 = __halves2half2(hl[2], hl[3]);
            __half2 q2 = __halves2half2(hl[4], hl[5]), q3 = __halves2half2(hl[6], hl[7]);
            ul.x = *(uint32_t*)&q0; ul.y = *(uint32_t*)&q1;
            ul.z = *(uint32_t*)&q2; ul.w = *(uint32_t*)&q3;
            *(uint4*)(smem + OG_AH + soff) = uh;
            *(uint4*)(smem + OG_AL + soff) = ul;
        }
        {
            const float4* srch = (const float4*)((const char*)g_Wh + kc * 65536);
            const float4* srcl = (const float4*)((const char*)g_Wl + kc * 65536);
            float4* dsth = (float4*)(smem + OG_WH);
            float4* dstl = (float4*)(smem + OG_WL);
#pragma unroll
            for (int i = 0; i < 8; ++i) {
                dsth[tid + i * 512] = srch[tid + i * 512];
                dstl[tid + i * 512] = srcl[tid + i * 512];
            }
        }
        __syncthreads();

#pragma unroll
        for (int ks = 0; ks < 4; ++ks) {
            const uint32_t aoff = (uint32_t)(((ks * 2 + acp) ^ arm) << 4);
            const uint32_t boff = (uint32_t)(((ks * 2 + bcp) ^ brm) << 4);
            uint32_t Ah0[4], Ah1[4], Al0[4], Al1[4];
            ldm4(Ah0, ah_base + aoff);
            ldm4(Ah1, ah_base + 16 * 128 + aoff);
            ldm4(Al0, al_base + aoff);
            ldm4(Al1, al_base + 16 * 128 + aoff);
#pragma unroll
            for (int nb = 0; nb < 4; ++nb) {
                uint32_t Bh[4], Bl[4];
                ldm4(Bh, bh_base + nb * 16 * 128 + boff);
                ldm4(Bl, bl_base + nb * 16 * 128 + boff);
                mma16816(d[0][nb * 2 + 0], Ah0, Bh[0], Bh[1]);
                mma16816(d[0][nb * 2 + 1], Ah0, Bh[2], Bh[3]);
                mma16816(d[1][nb * 2 + 0], Ah1, Bh[0], Bh[1]);
                mma16816(d[1][nb * 2 + 1], Ah1, Bh[2], Bh[3]);
                mma16816(d[0][nb * 2 + 0], Ah0, Bl[0], Bl[1]);
                mma16816(d[0][nb * 2 + 1], Ah0, Bl[2], Bl[3]);
                mma16816(d[1][nb * 2 + 0], Ah1, Bl[0], Bl[1]);
                mma16816(d[1][nb * 2 + 1], Ah1, Bl[2], Bl[3]);
                mma16816(d[0][nb * 2 + 0], Al0, Bh[0], Bh[1]);
                mma16816(d[0][nb * 2 + 1], Al0, Bh[2], Bh[3]);
                mma16816(d[1][nb * 2 + 0], Al1, Bh[0], Bh[1]);
                mma16816(d[1][nb * 2 + 1], Al1, Bh[2], Bh[3]);
            }
        }
    }

#pragma unroll
    for (int mt = 0; mt < 2; ++mt)
#pragma unroll
        for (int rw = 0; rw < 2; ++rw) {
            const int wordl = wm * 32 + mt * 16 + (lane >> 2) + rw * 8;
            const size_t row = (size_t)(w_base + wordl) * ODIM;
#pragma unroll
            for (int nt = 0; nt < 8; ++nt) {
                const int n0 = wn * 64 + nt * 8 + 2 * (lane & 3);
                float2 r;
                r.x = tanhf_fast(d[mt][nt][rw * 2 + 0] + b_out[n0]);
                r.y = tanhf_fast(d[mt][nt][rw * 2 + 1] + b_out[n0 + 1]);
                *(float2*)&out[row + n0] = r;
            }
        }
}

// ---------------- launch ----------------
extern "C" void kernel_launch(void* const* d_in, const int* in_sizes, int n_in,
                              void* d_out, int out_size) {
    const int* word_ids     = (const int*)d_in[0];
    const int* char_ids     = (const int*)d_in[1];
    const float* word_table = (const float*)d_in[2];
    const float* char_table = (const float*)d_in[3];
    const float* Wih_f = (const float*)d_in[4];
    const float* Whh_f = (const float*)d_in[5];
    const float* bih_f = (const float*)d_in[6];
    const float* bhh_f = (const float*)d_in[7];
    const float* Wih_b = (const float*)d_in[8];
    const float* Whh_b = (const float*)d_in[9];
    const float* bih_b = (const float*)d_in[10];
    const float* bhh_b = (const float*)d_in[11];
    const float* W_out = (const float*)d_in[12];
    const float* b_out = (const float*)d_in[13];
    float* out = (float*)d_out;

    cudaFuncSetAttribute(lstm_kernel, cudaFuncAttributeMaxDynamicSharedMemorySize, LSTM_SMEM);
    cudaFuncSetAttribute(outgemm_kernel, cudaFuncAttributeMaxDynamicSharedMemorySize, OG_SMEM);

    prep_all<<<360, 512>>>(char_table, Wih_f, bih_f, bhh_f, Wih_b, bih_b, bhh_b,
                           Whh_f, Whh_b, W_out);
    lstm_kernel<<<dim3(128, 2), 512, LSTM_SMEM>>>(char_ids);
    outgemm_kernel<<<128, 512, OG_SMEM>>>(word_ids, word_table, b_out, out);
}

// round 10
// speedup vs baseline: 9.3704x; 1.0527x over previous
#include <cuda_runtime.h>
#include <cuda_fp16.h>
#include <cstdint>

#define NW    8192
#define CL    16
#define CHID  128
#define GATES 512
#define CDIM  64
#define WDIM  300
#define ODIM  512
#define KREAL 556

// ---------------- device scratch ----------------
__device__ __align__(16) __half g_P16[2 * 128 * GATES];  // preproj fp16 [dir][ch][n=4j+ty], bias folded
__device__ __align__(16) __half g_B[2][GATES * CHID];    // Whh fp16, row-permuted + XOR8 swizzle
__device__ __align__(16) __half g_Wh[9 * 512 * 64];      // W_out hi fp16, 9 chunks, swizzled
__device__ __align__(16) __half g_Wl[9 * 512 * 64];      // W_out lo fp16
__device__ __align__(16) float  g_cf[NW * 256];

// ---------------- helpers ----------------
__device__ __forceinline__ uint32_t smem_u32(const void* p) {
    uint32_t a;
    asm("{ .reg .u64 t; cvta.to.shared.u64 t, %1; cvt.u32.u64 %0, t; }" : "=r"(a) : "l"(p));
    return a;
}
__device__ __forceinline__ float tanh_m(float x) {
    float y;
    asm("tanh.approx.f32 %0, %1;" : "=f"(y) : "f"(x));
    return y;
}
__device__ __forceinline__ float sig_m(float x) {
    return fmaf(0.5f, tanh_m(0.5f * x), 0.5f);
}
__device__ __forceinline__ float tanhf_fast(float x) {
    return 2.0f * __fdividef(1.0f, 1.0f + __expf(-2.0f * x)) - 1.0f;
}
__device__ __forceinline__ void ldm4(uint32_t* r, uint32_t addr) {
    asm volatile("ldmatrix.sync.aligned.m8n8.x4.shared.b16 {%0,%1,%2,%3}, [%4];"
                 : "=r"(r[0]), "=r"(r[1]), "=r"(r[2]), "=r"(r[3]) : "r"(addr));
}
__device__ __forceinline__ void mma16816(float* d, const uint32_t* a, uint32_t b0, uint32_t b1) {
    asm volatile("mma.sync.aligned.m16n8k16.row.col.f32.f16.f16.f32 "
                 "{%0,%1,%2,%3}, {%4,%5,%6,%7}, {%8,%9}, {%0,%1,%2,%3};"
                 : "+f"(d[0]), "+f"(d[1]), "+f"(d[2]), "+f"(d[3])
                 : "r"(a[0]), "r"(a[1]), "r"(a[2]), "r"(a[3]), "r"(b0), "r"(b1));
}
__device__ __forceinline__ void bar_half(int id) {
    asm volatile("bar.sync %0, 256;" :: "r"(id) : "memory");
}
__device__ __forceinline__ void cp16(uint32_t dst, const void* src) {
    asm volatile("cp.async.cg.shared.global [%0], [%1], 16;" :: "r"(dst), "l"(src) : "memory");
}
__device__ __forceinline__ void cp_commit() {
    asm volatile("cp.async.commit_group;" ::: "memory");
}
__device__ __forceinline__ void cp_wait0() {
    asm volatile("cp.async.wait_group 0;" ::: "memory");
}
__device__ __forceinline__ void lds128(uint32_t* q, uint32_t addr) {
    asm volatile("ld.shared.v4.b32 {%0,%1,%2,%3}, [%4];"
                 : "=r"(q[0]), "=r"(q[1]), "=r"(q[2]), "=r"(q[3]) : "r"(addr));
}

// ---------------- combined prep kernel ----------------
// blocks [0,256): P16 table (4-lane reduce); [256,288): Whh fp16; [288,360): W_out split
__global__ void prep_all(const float* __restrict__ ct,
                         const float* __restrict__ Wf, const float* __restrict__ bif,
                         const float* __restrict__ bhf,
                         const float* __restrict__ Wb, const float* __restrict__ bib,
                         const float* __restrict__ bhb,
                         const float* __restrict__ Whh_f, const float* __restrict__ Whh_b,
                         const float* __restrict__ W_out) {
    const int b = blockIdx.x, tid = threadIdx.x;
    __shared__ float cs[CDIM];
    if (b < 256) {
        // P16[dir][ch][n=4j+ty] = char_table[ch].Wih[ty*128+j] + bih + bhh (fp16)
        // 4 lanes per output: each lane dots 16 dims (coalesced float4), 2-shfl reduce.
        const int dir = b >> 7, ch = b & 127;
        const int g = tid >> 2, q = tid & 3;
        const float* W  = dir ? Wb : Wf;
        const float* bi = dir ? bib : bif;
        const float* bh = dir ? bhb : bhf;
        if (tid < CDIM) cs[tid] = ct[ch * CDIM + tid];
        __syncthreads();
        const float4* cc4 = (const float4*)&cs[q * 16];
        const float4 c0 = cc4[0], c1 = cc4[1], c2 = cc4[2], c3 = cc4[3];
#pragma unroll
        for (int p = 0; p < 4; ++p) {
            const int n = p * 128 + g;
            const int j = n >> 2, ty = n & 3, r = ty * CHID + j;
            const float4* wr = (const float4*)&W[r * CDIM + q * 16];
            const float4 w0 = wr[0], w1 = wr[1], w2 = wr[2], w3 = wr[3];
            float s = w0.x * c0.x + w0.y * c0.y + w0.z * c0.z + w0.w * c0.w;
            s += w1.x * c1.x + w1.y * c1.y + w1.z * c1.z + w1.w * c1.w;
            s += w2.x * c2.x + w2.y * c2.y + w2.z * c2.z + w2.w * c2.w;
            s += w3.x * c3.x + w3.y * c3.y + w3.z * c3.z + w3.w * c3.w;
            s += __shfl_xor_sync(0xFFFFFFFFu, s, 1);
            s += __shfl_xor_sync(0xFFFFFFFFu, s, 2);
            if (q == 0)
                g_P16[(((dir << 7) + ch) << 9) + n] = __float2half(s + bi[r] + bh[r]);
        }
    } else if (b < 288) {
        // Whh -> fp16 swizzled layout, one 16B chunk per thread
        const int cid = (b - 256) * 512 + tid;        // 16384
        const int dir = cid >> 13;
        const int rem = cid & 8191;
        const int rr = rem >> 4, cs_w = rem & 15;
        const int chunk = cs_w ^ (rr & 7);
        const int k0 = chunk * 8;
        const int j = ((rr >> 6) << 4) | (rr & 15);
        const int ty = (rr >> 4) & 3;
        const int r0 = ty * CHID + j;
        const float* W = dir ? Whh_b : Whh_f;
        const float4 f0 = *(const float4*)&W[r0 * CHID + k0];
        const float4 f1 = *(const float4*)&W[r0 * CHID + k0 + 4];
        __half2 h0 = __floats2half2_rn(f0.x, f0.y), h1 = __floats2half2_rn(f0.z, f0.w);
        __half2 h2 = __floats2half2_rn(f1.x, f1.y), h3 = __floats2half2_rn(f1.z, f1.w);
        uint4 u;
        u.x = *(uint32_t*)&h0; u.y = *(uint32_t*)&h1;
        u.z = *(uint32_t*)&h2; u.w = *(uint32_t*)&h3;
        *(uint4*)((char*)g_B[dir] + rr * 256 + cs_w * 16) = u;
    } else {
        // W_out -> split hi/lo fp16, one 16B chunk per thread per table
        const int cid = (b - 288) * 512 + tid;        // 36864
        const int kc = cid / 4096;
        const int rem = cid & 4095;
        const int n = rem >> 3, cs_w = rem & 7;
        const int chunk = cs_w ^ (n & 7);
        const int k0 = chunk * 8;
        float f[8];
#pragma unroll
        for (int i = 0; i < 8; ++i) {
            const int kk = kc * 64 + k0 + i;
            f[i] = (kk < KREAL) ? W_out[n * KREAL + kk] : 0.0f;
        }
        __half hh[8], hl[8];
#pragma unroll
        for (int i = 0; i < 8; ++i) {
            hh[i] = __float2half(f[i]);
            hl[i] = __float2half(f[i] - __half2float(hh[i]));
        }
        uint4 uh, ul;
        __half2 p0 = __halves2half2(hh[0], hh[1]), p1 = __halves2half2(hh[2], hh[3]);
        __half2 p2 = __halves2half2(hh[4], hh[5]), p3 = __halves2half2(hh[6], hh[7]);
        uh.x = *(uint32_t*)&p0; uh.y = *(uint32_t*)&p1;
        uh.z = *(uint32_t*)&p2; uh.w = *(uint32_t*)&p3;
        __half2 q0 = __halves2half2(hl[0], hl[1]), q1 = __halves2half2(hl[2], hl[3]);
        __half2 q2 = __halves2half2(hl[4], hl[5]), q3 = __halves2half2(hl[6], hl[7]);
        ul.x = *(uint32_t*)&q0; ul.y = *(uint32_t*)&q1;
        ul.z = *(uint32_t*)&q2; ul.w = *(uint32_t*)&q3;
        const uint32_t off = (uint32_t)(kc * 65536 + n * 128 + cs_w * 16);
        *(uint4*)((char*)g_Wh + off) = uh;
        *(uint4*)((char*)g_Wl + off) = ul;
    }
}

// ---------------- HMMA bidirectional char-LSTM with cp.async P pipeline ----------------
// grid (128,2): 64 words/CTA. 2 independent 8-warp halves; half 1 staggered ~900 cyc
// to force anti-phase pipe overlap (MUFU of one half under MMA of the other).
#define CI_OFF 0
#define A_OFF  4096
#define B_OFF  20480
#define P_OFF  151552
#define P_STRIDE 1072
#define LSTM_SMEM (P_OFF + 64 * P_STRIDE)   // 220160

__global__ __launch_bounds__(512, 1) void lstm_kernel(const int* __restrict__ char_ids) {
    extern __shared__ char smem[];
    const uint32_t sb = smem_u32(smem);
    int* ci_s = (int*)(smem + CI_OFF);

    const int tid = threadIdx.x, wid = tid >> 5, lane = tid & 31;
    const int dir = blockIdx.y;
    const int w_base = blockIdx.x * 64;
    const int wm = wid >> 3, wj = wid & 7;

    {
        const int* src = char_ids + (size_t)w_base * CL;
        ci_s[tid] = src[tid];
        ci_s[tid + 512] = src[tid + 512];
        float4* az = (float4*)(smem + A_OFF);
        az[tid] = make_float4(0.f, 0.f, 0.f, 0.f);
        az[tid + 512] = make_float4(0.f, 0.f, 0.f, 0.f);
        const float4* bsrc = (const float4*)g_B[dir];
        float4* bdst = (float4*)(smem + B_OFF);
#pragma unroll
        for (int i = 0; i < 16; ++i) bdst[tid + i * 512] = bsrc[tid + i * 512];
    }
    __syncthreads();

    // P prefetch roles
    const int pw = tid >> 3;
    const int pc0 = tid & 7;
    const uint32_t pdst0 = sb + P_OFF + pw * P_STRIDE;
    const char* psrc_dir = (const char*)g_P16 + ((size_t)dir << 17);

    // prologue: stage P(t0)
    {
        const int t0 = dir ? (CL - 1) : 0;
        const int ch = ci_s[pw * CL + t0];
        const char* srow = psrc_dir + ((size_t)ch << 10);
#pragma unroll
        for (int i = 0; i < 8; ++i) {
            const int c = pc0 + i * 8;
            cp16(pdst0 + c * 16, srow + c * 16);
        }
        cp_commit();
    }

    // phase stagger: half 1 delays ~900 cycles so the halves run anti-phased
    if (wm == 1) {
        long long t0 = clock64();
        while (clock64() - t0 < 900) {}
    }

    const int asub = lane >> 3;
    const int arow0 = wm * 32 + ((asub & 1) << 3) + (lane & 7);
    const int acp = asub >> 1;
    const int arm = arow0 & 7;
    const uint32_t a_base = sb + A_OFF + arow0 * 256;

    const int brow0 = wj * 64 + ((lane >> 4) << 3) + (lane & 7);
    const int bcp = (lane >> 3) & 1;
    const int brm = brow0 & 7;
    const uint32_t b_base = sb + B_OFF + brow0 * 256;

    const int mybar = 1 + wm;

    float d[2][8][4];
    float c_st[16], hs_st[16];
#pragma unroll
    for (int u = 0; u < 16; ++u) { c_st[u] = 0.f; hs_st[u] = 0.f; }

#pragma unroll 1
    for (int ti = 0; ti < CL; ++ti) {
        const int t = dir ? (CL - 1 - ti) : ti;

#pragma unroll
        for (int mt = 0; mt < 2; ++mt)
#pragma unroll
            for (int nt = 0; nt < 8; ++nt)
#pragma unroll
                for (int r = 0; r < 4; ++r) d[mt][nt][r] = 0.f;

        // gates = h(t-1) @ Whh^T
#pragma unroll
        for (int ks = 0; ks < 8; ++ks) {
            uint32_t A0[4], A1[4];
            ldm4(A0, a_base + (((ks * 2 + acp) ^ arm) << 4));
            ldm4(A1, a_base + 16 * 256 + (((ks * 2 + acp) ^ arm) << 4));
#pragma unroll
            for (int nb = 0; nb < 4; ++nb) {
                uint32_t B[4];
                ldm4(B, b_base + nb * 16 * 256 + (((ks * 2 + bcp) ^ brm) << 4));
                mma16816(d[0][nb * 2 + 0], A0, B[0], B[1]);
                mma16816(d[0][nb * 2 + 1], A0, B[2], B[3]);
                mma16816(d[1][nb * 2 + 0], A1, B[0], B[1]);
                mma16816(d[1][nb * 2 + 1], A1, B[2], B[3]);
            }
        }

        cp_wait0();
        bar_half(mybar);

        // epilogue: d += P(t), activations, c update, h sum, h(t) -> A
#pragma unroll
        for (int mt = 0; mt < 2; ++mt) {
#pragma unroll
            for (int rw = 0; rw < 2; ++rw) {
                const int wordl = wm * 32 + mt * 16 + (lane >> 2) + rw * 8;
#pragma unroll
                for (int jh = 0; jh < 2; ++jh) {
                    const int jg0 = wj * 16 + jh * 8 + 2 * (lane & 3);
                    uint32_t q[4];
                    lds128(q, sb + P_OFF + wordl * P_STRIDE + jg0 * 8);
                    float hv[2];
#pragma unroll
                    for (int rj = 0; rj < 2; ++rj) {
                        const float2 pa = __half22float2(*(__half2*)&q[rj * 2 + 0]);
                        const float2 pb = __half22float2(*(__half2*)&q[rj * 2 + 1]);
                        const int r = rw * 2 + rj;
                        const float gi = d[mt][0 + jh][r] + pa.x;
                        const float gf = d[mt][2 + jh][r] + pa.y;
                        const float gg = d[mt][4 + jh][r] + pb.x;
                        const float go = d[mt][6 + jh][r] + pb.y;
                        const int u = ((mt * 2 + rw) * 2 + jh) * 2 + rj;
                        const float cc = sig_m(gf) * c_st[u] + sig_m(gi) * tanh_m(gg);
                        c_st[u] = cc;
                        const float hh = sig_m(go) * tanh_m(cc);
                        hs_st[u] += hh;
                        hv[rj] = hh;
                    }
                    const int kk0 = wj * 16 + jh * 8 + 2 * (lane & 3);
                    const int chunk = kk0 >> 3;
                    const uint32_t off =
                        (uint32_t)(wordl * 256 + ((chunk ^ (wordl & 7)) << 4) + (kk0 & 7) * 2);
                    *(__half2*)(smem + A_OFF + off) = __floats2half2_rn(hv[0], hv[1]);
                }
            }
        }
        bar_half(mybar);

        // prefetch P(t+1)
        if (ti + 1 < CL) {
            const int tn = dir ? (t - 1) : (t + 1);
            const int ch = ci_s[pw * CL + tn];
            const char* srow = psrc_dir + ((size_t)ch << 10);
#pragma unroll
            for (int i = 0; i < 8; ++i) {
                const int c = pc0 + i * 8;
                cp16(pdst0 + c * 16, srow + c * 16);
            }
        }
        cp_commit();
    }

#pragma unroll
    for (int mt = 0; mt < 2; ++mt)
#pragma unroll
        for (int rw = 0; rw < 2; ++rw) {
            const int wordl = wm * 32 + mt * 16 + (lane >> 2) + rw * 8;
#pragma unroll
            for (int jh = 0; jh < 2; ++jh)
#pragma unroll
                for (int rj = 0; rj < 2; ++rj) {
                    const int jg = wj * 16 + jh * 8 + 2 * (lane & 3) + rj;
                    const int u = ((mt * 2 + rw) * 2 + jh) * 2 + rj;
                    g_cf[(size_t)(w_base + wordl) * 256 + dir * 128 + jg] = hs_st[u];
                }
        }
}

// ---------------- tensor-core output GEMM (split fp16, cp.async W staging) ----------------
#define OG_WID 0
#define OG_AH  1024
#define OG_AL  9216
#define OG_WH  17408
#define OG_WL  82944
#define OG_SMEM (OG_WL + 65536)   // 148480

__global__ __launch_bounds__(512, 1) void outgemm_kernel(const int* __restrict__ word_ids,
                                                         const float* __restrict__ word_table,
                                                         const float* __restrict__ b_out,
                                                         float* __restrict__ out) {
    extern __shared__ char smem[];
    const uint32_t sb = smem_u32(smem);
    int* wid_s = (int*)(smem + OG_WID);

    const int tid = threadIdx.x, wid = tid >> 5, lane = tid & 31;
    const int w_base = blockIdx.x * 64;
    const int wm = wid >> 3, wn = wid & 7;

    if (tid < 64) wid_s[tid] = word_ids[w_base + tid];
    __syncthreads();

    const int asub = lane >> 3;
    const int arow0 = wm * 32 + ((asub & 1) << 3) + (lane & 7);
    const int acp = asub >> 1;
    const int arm = arow0 & 7;
    const uint32_t ah_base = sb + OG_AH + arow0 * 128;
    const uint32_t al_base = sb + OG_AL + arow0 * 128;

    const int brow0 = wn * 64 + ((lane >> 4) << 3) + (lane & 7);
    const int bcp = (lane >> 3) & 1;
    const int brm = brow0 & 7;
    const uint32_t bh_base = sb + OG_WH + brow0 * 128;
    const uint32_t bl_base = sb + OG_WL + brow0 * 128;

    float d[2][8][4];
#pragma unroll
    for (int mt = 0; mt < 2; ++mt)
#pragma unroll
        for (int nt = 0; nt < 8; ++nt)
#pragma unroll
            for (int r = 0; r < 4; ++r) d[mt][nt][r] = 0.f;

    const int sm = tid >> 3;
    const int sk0 = (tid & 7) * 8;
    const int swid = wid_s[sm];
    const uint32_t soff = (uint32_t)(sm * 128 + (((sk0 >> 3) ^ (sm & 7)) << 4));

#pragma unroll 1
    for (int kc = 0; kc < 9; ++kc) {
        __syncthreads();   // previous MMA phase done reading buffers
        // 1. issue W hi/lo via cp.async FIRST (hidden behind feat gather/convert)
        {
            const char* srch = (const char*)g_Wh + kc * 65536;
            const char* srcl = (const char*)g_Wl + kc * 65536;
#pragma unroll
            for (int i = 0; i < 8; ++i) {
                const uint32_t bo = (uint32_t)(tid + i * 512) * 16;
                cp16(sb + OG_WH + bo, srch + bo);
                cp16(sb + OG_WL + bo, srcl + bo);
            }
            cp_commit();
        }
        // 2. feat gather + split + store (overlaps W transfer)
        {
            float f[8];
#pragma unroll
            for (int i = 0; i < 8; ++i) {
                const int kk = kc * 64 + sk0 + i;
                float v;
                if (kk < WDIM) v = word_table[(size_t)swid * WDIM + kk];
                else if (kk < KREAL) v = g_cf[(size_t)(w_base + sm) * 256 + (kk - WDIM)];
                else v = 0.0f;
                f[i] = v;
            }
            __half hh[8], hl[8];
#pragma unroll
            for (int i = 0; i < 8; ++i) {
                hh[i] = __float2half(f[i]);
                hl[i] = __float2half(f[i] - __half2float(hh[i]));
            }
            uint4 uh, ul;
            __half2 p0 = __halves2half2(hh[0], hh[1]), p1 = __halves2half2(hh[2], hh[3]);
            __half2 p2 = __halves2half2(hh[4], hh[5]), p3 = __halves2half2(hh[6], hh[7]);
            uh.x = *(uint32_t*)&p0; uh.y = *(uint32_t*)&p1;
            uh.z = *(uint32_t*)&p2; uh.w = *(uint32_t*)&p3;
            __half2 q0 = __halves2half2(hl[0], hl[1]), q1 = __halves2half2(hl[2], hl[3]);
            __half2 q2 = __halves2half2(hl[4], hl[5]), q3 = __halves2half2(hl[6], hl[7]);
            ul.x = *(uint32_t*)&q0; ul.y = *(uint32_t*)&q1;
            ul.z = *(uint32_t*)&q2; ul.w = *(uint32_t*)&q3;
            *(uint4*)(smem + OG_AH + soff) = uh;
            *(uint4*)(smem + OG_AL + soff) = ul;
        }
        // 3. wait for W, publish
        cp_wait0();
        __syncthreads();
        // 4. MMA phase
#pragma unroll
        for (int ks = 0; ks < 4; ++ks) {
            const uint32_t aoff = (uint32_t)(((ks * 2 + acp) ^ arm) << 4);
            const uint32_t boff = (uint32_t)(((ks * 2 + bcp) ^ brm) << 4);
            uint32_t Ah0[4], Ah1[4], Al0[4], Al1[4];
            ldm4(Ah0, ah_base + aoff);
            ldm4(Ah1, ah_base + 16 * 128 + aoff);
            ldm4(Al0, al_base + aoff);
            ldm4(Al1, al_base + 16 * 128 + aoff);
#pragma unroll
            for (int nb = 0; nb < 4; ++nb) {
                uint32_t Bh[4], Bl[4];
                ldm4(Bh, bh_base + nb * 16 * 128 + boff);
                ldm4(Bl, bl_base + nb * 16 * 128 + boff);
                mma16816(d[0][nb * 2 + 0], Ah0, Bh[0], Bh[1]);
                mma16816(d[0][nb * 2 + 1], Ah0, Bh[2], Bh[3]);
                mma16816(d[1][nb * 2 + 0], Ah1, Bh[0], Bh[1]);
                mma16816(d[1][nb * 2 + 1], Ah1, Bh[2], Bh[3]);
                mma16816(d[0][nb * 2 + 0], Ah0, Bl[0], Bl[1]);
                mma16816(d[0][nb * 2 + 1], Ah0, Bl[2], Bl[3]);
                mma16816(d[1][nb * 2 + 0], Ah1, Bl[0], Bl[1]);
                mma16816(d[1][nb * 2 + 1], Ah1, Bl[2], Bl[3]);
                mma16816(d[0][nb * 2 + 0], Al0, Bh[0], Bh[1]);
                mma16816(d[0][nb * 2 + 1], Al0, Bh[2], Bh[3]);
                mma16816(d[1][nb * 2 + 0], Al1, Bh[0], Bh[1]);
                mma16816(d[1][nb * 2 + 1], Al1, Bh[2], Bh[3]);
            }
        }
    }

#pragma unroll
    for (int mt = 0; mt < 2; ++mt)
#pragma unroll
        for (int rw = 0; rw < 2; ++rw) {
            const int wordl = wm * 32 + mt * 16 + (lane >> 2) + rw * 8;
            const size_t row = (size_t)(w_base + wordl) * ODIM;
#pragma unroll
            for (int nt = 0; nt < 8; ++nt) {
                const int n0 = wn * 64 + nt * 8 + 2 * (lane & 3);
                float2 r;
                r.x = tanhf_fast(d[mt][nt][rw * 2 + 0] + b_out[n0]);
                r.y = tanhf_fast(d[mt][nt][rw * 2 + 1] + b_out[n0 + 1]);
                *(float2*)&out[row + n0] = r;
            }
        }
}

// ---------------- launch ----------------
extern "C" void kernel_launch(void* const* d_in, const int* in_sizes, int n_in,
                              void* d_out, int out_size) {
    const int* word_ids     = (const int*)d_in[0];
    const int* char_ids     = (const int*)d_in[1];
    const float* word_table = (const float*)d_in[2];
    const float* char_table = (const float*)d_in[3];
    const float* Wih_f = (const float*)d_in[4];
    const float* Whh_f = (const float*)d_in[5];
    const float* bih_f = (const float*)d_in[6];
    const float* bhh_f = (const float*)d_in[7];
    const float* Wih_b = (const float*)d_in[8];
    const float* Whh_b = (const float*)d_in[9];
    const float* bih_b = (const float*)d_in[10];
    const float* bhh_b = (const float*)d_in[11];
    const float* W_out = (const float*)d_in[12];
    const float* b_out = (const float*)d_in[13];
    float* out = (float*)d_out;

    cudaFuncSetAttribute(lstm_kernel, cudaFuncAttributeMaxDynamicSharedMemorySize, LSTM_SMEM);
    cudaFuncSetAttribute(outgemm_kernel, cudaFuncAttributeMaxDynamicSharedMemorySize, OG_SMEM);

    prep_all<<<360, 512>>>(char_table, Wih_f, bih_f, bhh_f, Wih_b, bih_b, bhh_b,
                           Whh_f, Whh_b, W_out);
    lstm_kernel<<<dim3(128, 2), 512, LSTM_SMEM>>>(char_ids);
    outgemm_kernel<<<128, 512, OG_SMEM>>>(word_ids, word_table, b_out, out);
}